// round 14
// baseline (speedup 1.0000x reference)
#include <cuda_runtime.h>
#include <cuda_fp16.h>
#include <cstdint>

// ---------------- constants ----------------
#define OFF_IDX   1572864
#define OFF_LOSS  1574912
#define OFF_ZE    1574913
#define OUT_FULL  1705985

// ---------------- scratch (device globals) ----------------
__device__ uint32_t g_h1h[32 * 64 * 64 * 64];
__device__ uint32_t g_h1l[32 * 64 * 64 * 64];
__device__ float g_zp0[2048 * 64];                // proj partial, oc half 0
__device__ float g_zp1[2048 * 64];                // proj partial, oc half 1
__device__ unsigned long long g_best[2048];
__device__ uint32_t g_rh[2048 * 64];
__device__ uint32_t g_rl[2048 * 64];
__device__ float g_q[9 * 2048 * 128];
__device__ uint32_t g_wB2[36 * 4096];
__device__ uint32_t g_wt1B[36 * 4096];

// ---------------- PTX helpers ----------------
__device__ __forceinline__ uint32_t smem_u32(const void* p) {
    uint32_t a;
    asm("{ .reg .u64 t; cvta.to.shared.u64 t, %1; cvt.u32.u64 %0, t; }" : "=r"(a) : "l"(p));
    return a;
}
__device__ __forceinline__ void cp16(uint32_t dst, const void* src, uint32_t srcsize) {
    asm volatile("cp.async.cg.shared.global [%0], [%1], 16, %2;"
                 :: "r"(dst), "l"(src), "r"(srcsize) : "memory");
}
#define CP_COMMIT asm volatile("cp.async.commit_group;" ::: "memory")
#define CP_WAIT(n) asm volatile("cp.async.wait_group %0;" :: "n"(n) : "memory")

__device__ __forceinline__ uint32_t pack_h2(float a, float b) {
    __half2 h = __floats2half2_rn(a, b);
    return *(uint32_t*)&h;
}
__device__ __forceinline__ void split_pair(float x0, float x1, uint32_t& hi, uint32_t& lo) {
    __half h0 = __float2half_rn(x0), h1 = __float2half_rn(x1);
    hi = pack_h2(__half2float(h0), __half2float(h1));
    lo = pack_h2(x0 - __half2float(h0), x1 - __half2float(h1));
}
__device__ __forceinline__ void mma16816(float* c, const uint32_t* a, const uint32_t* b) {
    asm volatile(
        "mma.sync.aligned.m16n8k16.row.col.f32.f16.f16.f32 "
        "{%0,%1,%2,%3}, {%4,%5,%6,%7}, {%8,%9}, {%0,%1,%2,%3};"
        : "+f"(c[0]), "+f"(c[1]), "+f"(c[2]), "+f"(c[3])
        : "r"(a[0]), "r"(a[1]), "r"(a[2]), "r"(a[3]), "r"(b[0]), "r"(b[1]));
}
// packed fp32x2 fma (Blackwell FFMA2)
__device__ __forceinline__ void fma2(float2& d, const float2& a, const float2& b) {
    asm("fma.rn.f32x2 %0, %1, %2, %0;"
        : "+l"(*(unsigned long long*)&d)
        : "l"(*(const unsigned long long*)&a), "l"(*(const unsigned long long*)&b));
}

// ---------------- conv1: 3->128, 3x3, s2, p1, relu; FFMA2; split/packed/permuted ----------------
__global__ void k_conv1(const float* __restrict__ x, const float* __restrict__ w,
                        const float* __restrict__ b) {
    __shared__ float2 sw2[64 * 27];
    __shared__ float sb[128];
    int tid = threadIdx.x;
    int id = blockIdx.x;
    int n = id >> 4, yt = (id >> 2) & 3, xt = id & 3;
    {
        float* swf = (float*)sw2;
        for (int i = tid; i < 3456; i += 256) {
            int oc = i / 27, k = i - oc * 27;
            swf[((oc >> 1) * 27 + k) * 2 + (oc & 1)] = w[i];
        }
    }
    if (tid < 128) sb[tid] = b[tid];
    int ox = xt * 16 + (tid & 15);
    int oy = yt * 16 + (tid >> 4);
    float2 iv2[27];
    const float* xb = x + n * 3 * 16384;
#pragma unroll
    for (int c = 0; c < 3; c++)
#pragma unroll
        for (int di = 0; di < 3; di++) {
            int gy = 2 * oy + di - 1;
#pragma unroll
            for (int dj = 0; dj < 3; dj++) {
                int gx = 2 * ox + dj - 1;
                float v = 0.f;
                if (gy >= 0 && gy < 128 && gx >= 0 && gx < 128)
                    v = xb[(c * 128 + gy) * 128 + gx];
                iv2[c * 9 + di * 3 + dj] = make_float2(v, v);
            }
        }
    __syncthreads();
    int pos64 = ((n * 64 + oy) * 64 + ox) * 64;
    uint4* dh = (uint4*)(g_h1h + pos64);
    uint4* dl = (uint4*)(g_h1l + pos64);
#pragma unroll 1
    for (int g8 = 0; g8 < 8; g8++) {
        float2 acc2[8];
#pragma unroll
        for (int l = 0; l < 8; l++)
            acc2[l] = make_float2(sb[g8 * 16 + 2 * l], sb[g8 * 16 + 2 * l + 1]);
#pragma unroll
        for (int k = 0; k < 27; k++) {
            float2 vv = iv2[k];
#pragma unroll
            for (int l = 0; l < 8; l++)
                fma2(acc2[l], sw2[(g8 * 8 + l) * 27 + k], vv);
        }
        uint32_t hw[8], lw[8];
#pragma unroll
        for (int l = 0; l < 8; l++) {
            float a0 = fmaxf(acc2[l].x, 0.f);
            float a1 = fmaxf(acc2[l].y, 0.f);
            split_pair(a0, a1, hw[l], lw[l]);
        }
        uint4 c0, c1;
        c0.x = hw[0]; c0.y = hw[4]; c0.z = hw[1]; c0.w = hw[5];
        c1.x = hw[2]; c1.y = hw[6]; c1.z = hw[3]; c1.w = hw[7];
        dh[g8 * 2] = c0; dh[g8 * 2 + 1] = c1;
        c0.x = lw[0]; c0.y = lw[4]; c0.z = lw[1]; c0.w = lw[5];
        c1.x = lw[2]; c1.y = lw[6]; c1.z = lw[3]; c1.w = lw[7];
        dl[g8 * 2] = c0; dl[g8 * 2 + 1] = c1;
    }
}

// ---------------- prep: both weight tensors -> fp16 hi/lo fragment-native ----------------
__global__ void k_prep(const float* __restrict__ w2, const float* __restrict__ w1d) {
    int pid = blockIdx.x * 256 + threadIdx.x;
    int j = pid & 3;
    int lane = (pid >> 2) & 31;
    int ni = (pid >> 7) & 7;
    int kc = (pid >> 10) & 1;
    int wn = (pid >> 11) & 1;
    int stage = pid >> 12;
    int lg = lane >> 2, lt = lane & 3;
    int oc = wn * 64 + ni * 8 + lg;
    int kloc = kc * 16 + 2 * lt + ((j & 1) ? 8 : 0);
    int cs = stage & 3;
    int c0 = cs * 32 + kloc;
    {
        int tap = stage >> 2;
        float w0 = w2[(oc * 128 + c0) * 9 + tap];
        float w1 = w2[(oc * 128 + c0 + 1) * 9 + tap];
        uint32_t hi, lo;
        split_pair(w0, w1, hi, lo);
        g_wB2[pid] = (j < 2) ? hi : lo;
    }
    {
        int t = stage >> 2;
        float w0 = w1d[(oc * 128 + c0) * 9 + t];
        float w1 = w1d[(oc * 128 + c0 + 1) * 9 + t];
        uint32_t hi, lo;
        split_pair(w0, w1, hi, lo);
        g_wt1B[pid] = (j < 2) ? hi : lo;
    }
}

// ---------------- init: g_best ----------------
__global__ void k_init() {
    int i = blockIdx.x * 256 + threadIdx.x;
    if (i < 2048) g_best[i] = 0xFFFFFFFFFFFFFFFFull;
}

// ---------------- conv2: M=128 x N=64 per CTA, 128 thr, 4 CTA/SM, double-buffered ----------------
#define D2_AT 18432                     // A tile bytes (128 rows * 144)
#define D2_BT 8192                      // B tile bytes (half oc: 2048 u32)
#define D2_BUF (D2_AT + D2_BT)          // 26624
#define D2_EPI (34816 + 2176 + 17408)   // eb + sp + spw = 54400
#define D2_SMEM ((D2_EPI > 2 * D2_BUF) ? D2_EPI : (2 * D2_BUF))

__global__ __launch_bounds__(128, 4) void k_conv2m(const float* __restrict__ b2,
                                                   const float* __restrict__ pw) {
    extern __shared__ char sm[];
    uint32_t smb = smem_u32(sm);
    int tid = threadIdx.x;
    int warp = tid >> 5, lane = tid & 31;
    int lg = lane >> 2, lt = lane & 3;
    int bid = blockIdx.x;
    int h = bid & 1, t = (bid >> 1) & 7, n = bid >> 4;

    // ---- A loader per-thread constants (uniform j-strides) ----
    int m0 = tid >> 3;                 // 0..15
    int kind = (tid >> 2) & 1;
    int u = tid & 3;
    const uint32_t* agb = kind ? g_h1l : g_h1h;
    const uint32_t* abase = agb + (((n * 64 + 8 * t - 1) * 64) + (2 * m0 - 1)) * 64 + u * 4;
    uint32_t adst0 = (uint32_t)(m0 * 144 + kind * 64 + u * 16);
    bool ty0 = (t == 0);
    bool mx0 = (m0 == 0);
    const uint32_t* bsrc = g_wB2 + h * 2048 + tid * 4;
    uint32_t bdst0 = (uint32_t)(D2_AT + tid * 16);

#define D2_LOAD(sidx)                                                              \
    do {                                                                           \
        int s_ = (sidx);                                                           \
        int tap_ = s_ >> 2, cs_ = s_ & 3;                                          \
        int di_ = tap_ / 3, dj_ = tap_ % 3;                                        \
        bool dy_ = (di_ > 0), dx_ = (dj_ > 0);                                     \
        int off_ = di_ * 4096 + dj_ * 64 + cs_ * 16;                               \
        uint32_t bb_ = smb + (uint32_t)((s_ & 1) * D2_BUF);                        \
        _Pragma("unroll")                                                          \
        for (int j_ = 0; j_ < 8; j_++) {                                           \
            bool y0_ = ty0 && (j_ < 2);                                            \
            bool x0_ = mx0 && ((j_ & 1) == 0);                                     \
            bool ok_ = (dy_ || !y0_) && (dx_ || !x0_);                             \
            const uint32_t* src_ = ok_                                             \
                ? (abase + off_ + (j_ & 1) * 2048 + (j_ >> 1) * 8192)              \
                : (const uint32_t*)g_h1h;                                          \
            cp16(bb_ + adst0 + (uint32_t)(j_ * 2304), src_, ok_ ? 16u : 0u);       \
        }                                                                          \
        const uint32_t* bs_ = bsrc + s_ * 4096;                                    \
        _Pragma("unroll")                                                          \
        for (int j_ = 0; j_ < 4; j_++)                                             \
            cp16(bb_ + bdst0 + (uint32_t)(j_ * 2048), bs_ + j_ * 512, 16u);        \
        CP_COMMIT;                                                                 \
    } while (0)

    float acc[2][8][4];
#pragma unroll
    for (int mi = 0; mi < 2; mi++)
#pragma unroll
        for (int ni = 0; ni < 8; ni++)
#pragma unroll
            for (int r = 0; r < 4; r++) acc[mi][ni][r] = 0.f;

    D2_LOAD(0);

    for (int s = 0; s < 36; s++) {
        if (s + 1 < 36) { D2_LOAD(s + 1); CP_WAIT(1); } else { CP_WAIT(0); }
        __syncthreads();
        const uint32_t* As = (const uint32_t*)(sm + (s & 1) * D2_BUF);
        const uint32_t* Bs = (const uint32_t*)(sm + (s & 1) * D2_BUF + D2_AT);
#pragma unroll
        for (int kc = 0; kc < 2; kc++) {
            uint32_t ahi[2][4], alo[2][4];
#pragma unroll
            for (int mi = 0; mi < 2; mi++) {
                int r = warp * 32 + mi * 16 + lg;
                uint2 h0 = *(const uint2*)(As + r * 36 + kc * 8 + 2 * lt);
                uint2 h1 = *(const uint2*)(As + (r + 8) * 36 + kc * 8 + 2 * lt);
                uint2 l0 = *(const uint2*)(As + r * 36 + 16 + kc * 8 + 2 * lt);
                uint2 l1 = *(const uint2*)(As + (r + 8) * 36 + 16 + kc * 8 + 2 * lt);
                ahi[mi][0] = h0.x; ahi[mi][1] = h1.x; ahi[mi][2] = h0.y; ahi[mi][3] = h1.y;
                alo[mi][0] = l0.x; alo[mi][1] = l1.x; alo[mi][2] = l0.y; alo[mi][3] = l1.y;
            }
#pragma unroll
            for (int ni = 0; ni < 8; ni++) {
                uint4 bv = *(const uint4*)(Bs + ((kc * 8 + ni) * 32 + lane) * 4);
                uint32_t bh[2] = {bv.x, bv.y};
                uint32_t bl[2] = {bv.z, bv.w};
#pragma unroll
                for (int mi = 0; mi < 2; mi++) {
                    mma16816(acc[mi][ni], ahi[mi], bh);
                    mma16816(acc[mi][ni], alo[mi], bh);
                    mma16816(acc[mi][ni], ahi[mi], bl);
                }
            }
        }
        __syncthreads();
    }

    // ---- epilogue: acc -> eb; pool -> sp; partial proj -> g_zp[h] ----
    float* eb  = (float*)sm;                 // [128][68]
    float* sp  = (float*)(sm + 34816);       // [8][68]
    float* spw = (float*)(sm + 36992);       // [64][68]
#pragma unroll
    for (int mi = 0; mi < 2; mi++)
#pragma unroll
        for (int ni = 0; ni < 8; ni++) {
            int m = warp * 32 + mi * 16 + lg;
            int oc = ni * 8 + 2 * lt;
            eb[m * 68 + oc]           = acc[mi][ni][0];
            eb[m * 68 + oc + 1]       = acc[mi][ni][1];
            eb[(m + 8) * 68 + oc]     = acc[mi][ni][2];
            eb[(m + 8) * 68 + oc + 1] = acc[mi][ni][3];
        }
    for (int i = tid; i < 1024; i += 128) {
        int d = i >> 4, c4 = i & 15;
        float4 v = *(const float4*)(pw + d * 128 + h * 64 + c4 * 4);
        *(float4*)(spw + d * 68 + c4 * 4) = v;
    }
    __syncthreads();
    for (int i = tid; i < 512; i += 128) {
        int pc = i >> 6, oc = i & 63;
        float bv = __ldg(&b2[h * 64 + oc]);
        float s = 0.f;
#pragma unroll
        for (int oyl = 0; oyl < 4; oyl++)
#pragma unroll
            for (int dx = 0; dx < 4; dx++) {
                int m = oyl * 32 + pc * 4 + dx;
                s += fmaxf(eb[m * 68 + oc] + bv, 0.f);
            }
        sp[pc * 68 + oc] = s * (1.f / 16.f);
    }
    __syncthreads();
    float* zp = h ? g_zp1 : g_zp0;
    for (int i = tid; i < 512; i += 128) {
        int pos = i >> 6, d = i & 63;
        float accz = 0.f;
#pragma unroll 8
        for (int c4 = 0; c4 < 16; c4++) {
            float4 wv = *(const float4*)(spw + d * 68 + c4 * 4);
            float4 hv = *(const float4*)(sp + pos * 68 + c4 * 4);
            accz = fmaf(wv.x, hv.x, accz);
            accz = fmaf(wv.y, hv.y, accz);
            accz = fmaf(wv.z, hv.z, accz);
            accz = fmaf(wv.w, hv.w, accz);
        }
        zp[(n * 64 + t * 8 + pos) * 64 + d] = accz;
    }
}

// ---------------- vector quantizer: sums proj partials + bias; writes z_e out ----------------
#define VQ_SMEMF (256 * 68 + 16 * 68 + 16 + 16 * 4 * 2)
__global__ __launch_bounds__(256) void k_vq(const float* __restrict__ cb,
                                            const float* __restrict__ pb,
                                            float* __restrict__ dout, int wout) {
    extern __shared__ float smv[];
    float* scb = smv;
    float* szt = smv + 256 * 68;
    float* szn = szt + 16 * 68;
    float* red = szn + 16;
    int tid = threadIdx.x;
    int pg = blockIdx.x >> 1, half = blockIdx.x & 1;
    for (int i = tid; i < 256 * 16; i += 256) {
        int c = i >> 4, dd = i & 15;
        float4 v = *(const float4*)(cb + (half * 256 + c) * 64 + dd * 4);
        *(float4*)(scb + c * 68 + dd * 4) = v;
    }
    for (int i = tid; i < 16 * 16; i += 256) {
        int p = i >> 4, dd = i & 15;
        int gp = pg * 16 + p;
        float4 a = *(const float4*)(g_zp0 + gp * 64 + dd * 4);
        float4 b4 = *(const float4*)(g_zp1 + gp * 64 + dd * 4);
        float4 c4 = *(const float4*)(pb + dd * 4);
        float4 v;
        v.x = c4.x + a.x + b4.x;
        v.y = c4.y + a.y + b4.y;
        v.z = c4.z + a.z + b4.z;
        v.w = c4.w + a.w + b4.w;
        *(float4*)(szt + p * 68 + dd * 4) = v;
    }
    __syncthreads();
    if (wout && half == 0) {
        for (int i = tid; i < 1024; i += 256) {
            int pl = i >> 6, d = i & 63;
            int gp = pg * 16 + pl;
            dout[OFF_ZE + ((gp >> 6) * 64 + d) * 64 + (gp & 63)] = szt[pl * 68 + d];
        }
    }
    if (tid < 16) {
        float s = 0.f;
#pragma unroll 8
        for (int d = 0; d < 64; d++) { float z = szt[tid * 68 + d]; s = fmaf(z, z, s); }
        szn[tid] = s;
    }
    __syncthreads();
    int warp = tid >> 5, lane = tid & 31;
    int q = warp & 3, hh = warp >> 2;

    float dot[2][8], csq[2];
#pragma unroll
    for (int i = 0; i < 2; i++) {
        csq[i] = 0.f;
#pragma unroll
        for (int p = 0; p < 8; p++) dot[i][p] = 0.f;
    }
#pragma unroll 2
    for (int d4 = 0; d4 < 16; d4++) {
        float4 zz[8];
#pragma unroll
        for (int p = 0; p < 8; p++)
            zz[p] = *(const float4*)(szt + (hh * 8 + p) * 68 + d4 * 4);
#pragma unroll
        for (int i = 0; i < 2; i++) {
            float4 cc = *(const float4*)(scb + (q * 64 + lane + i * 32) * 68 + d4 * 4);
            csq[i] = fmaf(cc.x, cc.x, csq[i]);
            csq[i] = fmaf(cc.y, cc.y, csq[i]);
            csq[i] = fmaf(cc.z, cc.z, csq[i]);
            csq[i] = fmaf(cc.w, cc.w, csq[i]);
#pragma unroll
            for (int p = 0; p < 8; p++) {
                float tt = dot[i][p];
                tt = fmaf(cc.x, zz[p].x, tt);
                tt = fmaf(cc.y, zz[p].y, tt);
                tt = fmaf(cc.z, zz[p].z, tt);
                tt = fmaf(cc.w, zz[p].w, tt);
                dot[i][p] = tt;
            }
        }
    }
#pragma unroll
    for (int p = 0; p < 8; p++) {
        float zn = szn[hh * 8 + p];
        float bd = 3.4e38f; int bi = 0;
#pragma unroll
        for (int i = 0; i < 2; i++) {
            float dist = zn + csq[i] - 2.f * dot[i][p];
            int idx = half * 256 + q * 64 + lane + i * 32;
            if (dist < bd) { bd = dist; bi = idx; }
        }
#pragma unroll
        for (int off = 16; off > 0; off >>= 1) {
            float od = __shfl_down_sync(0xffffffffu, bd, off);
            int   oi = __shfl_down_sync(0xffffffffu, bi, off);
            if (od < bd || (od == bd && oi < bi)) { bd = od; bi = oi; }
        }
        if (lane == 0) {
            red[((hh * 8 + p) * 4 + q) * 2]     = bd;
            red[((hh * 8 + p) * 4 + q) * 2 + 1] = __int_as_float(bi);
        }
    }
    __syncthreads();
    if (tid < 16) {
        float bd = 3.4e38f; int bi = 0;
#pragma unroll
        for (int qq = 0; qq < 4; qq++) {
            float od = red[(tid * 4 + qq) * 2];
            int   oi = __float_as_int(red[(tid * 4 + qq) * 2 + 1]);
            if (od < bd || (od == bd && oi < bi)) { bd = od; bi = oi; }
        }
        unsigned long long key = (((unsigned long long)__float_as_uint(bd)) << 32)
                               | (unsigned long long)(unsigned)bi;
        atomicMin(&g_best[pg * 16 + tid], key);
    }
}

// ---------------- decoder 1x1 dproj + relu -> split/packed/permuted g_rh/g_rl ----------------
__global__ void k_dec_r(const float* __restrict__ cb, const float* __restrict__ dpw,
                        const float* __restrict__ dpb) {
    __shared__ float sdw[128 * 65];
    __shared__ float scr[8][64];
    __shared__ float srr[8][128];
    int tid = threadIdx.x;
    for (int i = tid; i < 128 * 64; i += 128) {
        int c = i >> 6, d = i & 63;
        sdw[c * 65 + d] = dpw[i];
    }
    for (int i = tid; i < 8 * 64; i += 128) {
        int pl = i >> 6, d = i & 63;
        int p = blockIdx.x * 8 + pl;
        int idx = (int)(g_best[p] & 0xFFFFFFFFull);
        scr[pl][d] = cb[idx * 64 + d];
    }
    __syncthreads();
    int c = tid;
    float bv = dpb[c];
    for (int pl = 0; pl < 8; pl++) {
        float acc = bv;
#pragma unroll 4
        for (int d = 0; d < 64; d++) acc = fmaf(sdw[c * 65 + d], scr[pl][d], acc);
        srr[pl][c] = fmaxf(acc, 0.f);
    }
    __syncthreads();
    for (int i = tid; i < 8 * 64; i += 128) {
        int pl = i >> 6, pr = i & 63;
        float x0 = srr[pl][2 * pr], x1 = srr[pl][2 * pr + 1];
        uint32_t hi, lo;
        split_pair(x0, x1, hi, lo);
        int blk = pr >> 3, ii = pr & 7;
        int pos = blk * 8 + ((ii < 4) ? 2 * ii : 2 * ii - 7);
        int p = blockIdx.x * 8 + pl;
        g_rh[p * 64 + pos] = hi;
        g_rl[p * 64 + pos] = lo;
    }
}

// ---------------- q = r @ wt1 per tap, tensor fp16x2 (double-buffered, 3-pass) ----------------
#define C2_AT 18432
#define C2_BT 16384
#define C2_BUFB (C2_AT + C2_BT)
#define QM_SMEM_MAIN (2 * C2_BUFB)
__device__ __forceinline__ void qm_load_stage(uint32_t smb, int buf, int s,
                                              int gt, int t, int tid) {
    uint32_t bb = smb + buf * C2_BUFB;
#pragma unroll
    for (int j = 0; j < 4; j++) {
        int c = j * 256 + tid;
        int m = c >> 3, q = c & 7;
        int kind = q >> 2, u = q & 3;
        const uint32_t* gbase = kind ? g_rl : g_rh;
        cp16(bb + m * 144 + kind * 64 + u * 16,
             gbase + (gt * 128 + m) * 64 + s * 16 + u * 4, 16u);
    }
#pragma unroll
    for (int j = 0; j < 4; j++) {
        int c = j * 256 + tid;
        cp16(bb + C2_AT + c * 16, g_wt1B + (t * 4 + s) * 4096 + c * 4, 16u);
    }
    CP_COMMIT;
}

__global__ __launch_bounds__(256, 2) void k_qm() {
    extern __shared__ char sm[];
    uint32_t smb = smem_u32(sm);
    int tid = threadIdx.x;
    int warp = tid >> 5, lane = tid & 31;
    int wm = warp >> 1, wn = warp & 1;
    int lg = lane >> 2, lt = lane & 3;
    int gt = blockIdx.x, t = blockIdx.y;

    float acc[2][8][4];
#pragma unroll
    for (int mi = 0; mi < 2; mi++)
#pragma unroll
        for (int ni = 0; ni < 8; ni++)
#pragma unroll
            for (int r = 0; r < 4; r++) acc[mi][ni][r] = 0.f;

    qm_load_stage(smb, 0, 0, gt, t, tid);
    for (int s = 0; s < 4; s++) {
        int buf = s & 1;
        if (s + 1 < 4) qm_load_stage(smb, buf ^ 1, s + 1, gt, t, tid);
        if (s + 1 < 4) { CP_WAIT(1); } else { CP_WAIT(0); }
        __syncthreads();
        const uint32_t* As = (const uint32_t*)(sm + buf * C2_BUFB);
        const uint32_t* Bs = (const uint32_t*)(sm + buf * C2_BUFB + C2_AT);
#pragma unroll
        for (int kc = 0; kc < 2; kc++) {
            uint32_t ahi[2][4], alo[2][4];
#pragma unroll
            for (int mi = 0; mi < 2; mi++) {
                int r = wm * 32 + mi * 16 + lg;
                uint2 h0 = *(const uint2*)(As + r * 36 + kc * 8 + 2 * lt);
                uint2 h1 = *(const uint2*)(As + (r + 8) * 36 + kc * 8 + 2 * lt);
                uint2 l0 = *(const uint2*)(As + r * 36 + 16 + kc * 8 + 2 * lt);
                uint2 l1 = *(const uint2*)(As + (r + 8) * 36 + 16 + kc * 8 + 2 * lt);
                ahi[mi][0] = h0.x; ahi[mi][1] = h1.x; ahi[mi][2] = h0.y; ahi[mi][3] = h1.y;
                alo[mi][0] = l0.x; alo[mi][1] = l1.x; alo[mi][2] = l0.y; alo[mi][3] = l1.y;
            }
            uint32_t bh[8][2], bl[8][2];
#pragma unroll
            for (int ni = 0; ni < 8; ni++) {
                uint4 bv = *(const uint4*)(Bs + (((wn * 2 + kc) * 8 + ni) * 32 + lane) * 4);
                bh[ni][0] = bv.x; bh[ni][1] = bv.y;
                bl[ni][0] = bv.z; bl[ni][1] = bv.w;
            }
#pragma unroll
            for (int ni = 0; ni < 8; ni++)
#pragma unroll
                for (int mi = 0; mi < 2; mi++)
                    mma16816(acc[mi][ni], ahi[mi], bh[ni]);
#pragma unroll
            for (int ni = 0; ni < 8; ni++)
#pragma unroll
                for (int mi = 0; mi < 2; mi++)
                    mma16816(acc[mi][ni], alo[mi], bh[ni]);
#pragma unroll
            for (int ni = 0; ni < 8; ni++)
#pragma unroll
                for (int mi = 0; mi < 2; mi++)
                    mma16816(acc[mi][ni], ahi[mi], bl[ni]);
        }
        __syncthreads();
    }
    float* eb = (float*)sm;
#pragma unroll
    for (int mi = 0; mi < 2; mi++)
#pragma unroll
        for (int ni = 0; ni < 8; ni++) {
            int m = wm * 32 + mi * 16 + lg;
            int oc = wn * 64 + ni * 8 + 2 * lt;
            eb[m * 132 + oc]           = acc[mi][ni][0];
            eb[m * 132 + oc + 1]       = acc[mi][ni][1];
            eb[(m + 8) * 132 + oc]     = acc[mi][ni][2];
            eb[(m + 8) * 132 + oc + 1] = acc[mi][ni][3];
        }
    __syncthreads();
    for (int i = tid; i < 4096; i += 256) {
        int m = i >> 5, o4 = i & 31;
        float4 v;
        v.x = eb[m * 132 + o4 * 4];
        v.y = eb[m * 132 + o4 * 4 + 1];
        v.z = eb[m * 132 + o4 * 4 + 2];
        v.w = eb[m * 132 + o4 * 4 + 3];
        *(float4*)(g_q + (t * 2048 + gt * 128 + m) * 128 + o4 * 4) = v;
    }
}

// ---------------- per-block pixel types + FUSED x_hat scatter + idx/loss tail ----------------
__global__ void k_xblk(const float* __restrict__ b1d, const float* __restrict__ dw2,
                       const float* __restrict__ db2, float* __restrict__ dout, int wout) {
    if (blockIdx.x >= 2048) {
        if (!wout) return;
        int tid = threadIdx.x;
        if (blockIdx.x < 2064) {
            int fid = (blockIdx.x - 2048) * 128 + tid;
            dout[OFF_IDX + fid] = (float)(unsigned)(g_best[fid] & 0xFFFFFFFFull);
        } else {
            __shared__ float sred[128];
            float s = 0.f;
#pragma unroll
            for (int k = 0; k < 16; k++) {
                int p = k * 128 + tid;
                s += __uint_as_float((unsigned)(g_best[p] >> 32));
            }
            sred[tid] = s;
            __syncthreads();
            for (int off = 64; off > 0; off >>= 1) {
                if (tid < off) sred[tid] += sred[tid + off];
                __syncthreads();
            }
            if (tid == 0) dout[OFF_LOSS] = 1.25f * sred[0] * (1.0f / 131072.0f);
        }
        return;
    }
    __shared__ float sz[9 * 132];
    __shared__ float sxo[27];
    __shared__ float sw2[3 * 128];
    int g = blockIdx.x;
    int n = g >> 6, bi = (g >> 3) & 7, bj = g & 7;
    int o = threadIdx.x;
    for (int i = o; i < 384; i += 128) sw2[i] = dw2[i];
    float bo = b1d[o];
    float s[3][3];
#pragma unroll
    for (int ti = 0; ti < 3; ti++)
#pragma unroll
        for (int tj = 0; tj < 3; tj++) s[ti][tj] = bo;
    const int OFF[3][2]  = {{-1, 0}, {0, 0}, {1, 0}};
    const int MSK[3][2]  = {{1, 6}, {7, 0}, {4, 3}};
#pragma unroll
    for (int di = 0; di < 3; di++)
#pragma unroll
        for (int dj = 0; dj < 3; dj++) {
            const float* qb = g_q + ((di * 3 + dj) * 2048 + n * 64) * 128 + o;
#pragma unroll
            for (int a = 0; a < 2; a++) {
                int tim = MSK[di][a];
                if (tim == 0) continue;
                int roff = OFF[di][a];
                int bi2 = bi + roff;
#pragma unroll
                for (int bb = 0; bb < 2; bb++) {
                    int tjm = MSK[dj][bb];
                    if (tjm == 0) continue;
                    int coff = OFF[dj][bb];
                    int bj2 = bj + coff;
                    float v = 0.f;
                    if (bi2 >= 0 && bi2 < 8 && bj2 >= 0 && bj2 < 8)
                        v = qb[(bi2 * 8 + bj2) * 128];
#pragma unroll
                    for (int ti = 0; ti < 3; ti++)
                        if ((tim >> ti) & 1)
#pragma unroll
                            for (int tj = 0; tj < 3; tj++)
                                if ((tjm >> tj) & 1) s[ti][tj] += v;
                }
            }
        }
#pragma unroll
    for (int ti = 0; ti < 3; ti++)
#pragma unroll
        for (int tj = 0; tj < 3; tj++)
            sz[(ti * 3 + tj) * 132 + o] = fmaxf(s[ti][tj], 0.f);
    __syncthreads();
    if (o < 27) {
        int ty = o / 3, co = o % 3;
        float acc = db2[co];
#pragma unroll 4
        for (int c = 0; c < 128; c++)
            acc = fmaf(sw2[co * 128 + c], sz[ty * 132 + c], acc);
        sxo[ty * 3 + co] = acc;
    }
    __syncthreads();
    float* xb = dout + ((size_t)n * 3) * 16384 + (bi * 16) * 128 + bj * 16;
    for (int e = o; e < 768; e += 128) {
        int j = e & 15, i2 = (e >> 4) & 15, c = e >> 8;
        int ti = (i2 == 0) ? 0 : ((i2 == 15) ? 2 : 1);
        int tj = (j == 0) ? 0 : ((j == 15) ? 2 : 1);
        xb[(c * 128 + i2) * 128 + j] = sxo[(ti * 3 + tj) * 3 + c];
    }
}

// ---------------- launcher ----------------
extern "C" void kernel_launch(void* const* d_in, const int* in_sizes, int n_in,
                              void* d_out, int out_size) {
    const float* x   = (const float*)d_in[0];
    const float* w1  = (const float*)d_in[1];
    const float* b1  = (const float*)d_in[2];
    const float* w2  = (const float*)d_in[3];
    const float* b2  = (const float*)d_in[4];
    const float* pw  = (const float*)d_in[5];
    const float* pb  = (const float*)d_in[6];
    const float* cb  = (const float*)d_in[7];
    const float* dpw = (const float*)d_in[8];
    const float* dpb = (const float*)d_in[9];
    const float* w1d = (const float*)d_in[10];
    const float* b1d = (const float*)d_in[11];
    const float* dw2 = (const float*)d_in[12];
    const float* db2 = (const float*)d_in[13];
    float* out = (float*)d_out;

    cudaFuncSetAttribute(k_conv2m, cudaFuncAttributeMaxDynamicSharedMemorySize, D2_SMEM);
    cudaFuncSetAttribute(k_qm, cudaFuncAttributeMaxDynamicSharedMemorySize, QM_SMEM_MAIN);
    cudaFuncSetAttribute(k_vq, cudaFuncAttributeMaxDynamicSharedMemorySize, VQ_SMEMF * 4);

    int wout = (out_size >= OUT_FULL) ? 1 : 0;

    k_conv1<<<512, 256>>>(x, w1, b1);                       // 1
    k_prep<<<576, 256>>>(w2, w1d);                          // 2
    k_init<<<8, 256>>>();                                   // 3
    k_conv2m<<<512, 128, D2_SMEM>>>(b2, pw);                // 4  <- profiled
    k_vq<<<256, 256, VQ_SMEMF * 4>>>(cb, pb, out, wout);    // 5
    k_dec_r<<<256, 128>>>(cb, dpw, dpb);                    // 6
    k_qm<<<dim3(16, 9), 256, QM_SMEM_MAIN>>>();             // 7
    k_xblk<<<2065, 128>>>(b1d, dw2, db2, out, wout);        // 8
}

// round 15
// speedup vs baseline: 1.0356x; 1.0356x over previous
#include <cuda_runtime.h>
#include <cuda_fp16.h>
#include <cstdint>

// ---------------- constants ----------------
#define OFF_IDX   1572864
#define OFF_LOSS  1574912
#define OFF_ZE    1574913
#define OUT_FULL  1705985

// ---------------- scratch (device globals) ----------------
__device__ uint32_t g_h1h[32 * 64 * 64 * 64];
__device__ uint32_t g_h1l[32 * 64 * 64 * 64];
__device__ float g_ze[2048 * 64];
__device__ unsigned long long g_best[2048];
__device__ uint32_t g_rh[2048 * 64];
__device__ uint32_t g_rl[2048 * 64];
__device__ float g_q[9 * 2048 * 128];
__device__ uint32_t g_wB2[36 * 4096];
__device__ uint32_t g_wt1B[36 * 4096];

// ---------------- PTX helpers ----------------
__device__ __forceinline__ uint32_t smem_u32(const void* p) {
    uint32_t a;
    asm("{ .reg .u64 t; cvta.to.shared.u64 t, %1; cvt.u32.u64 %0, t; }" : "=r"(a) : "l"(p));
    return a;
}
__device__ __forceinline__ void cp16(uint32_t dst, const void* src, uint32_t srcsize) {
    asm volatile("cp.async.cg.shared.global [%0], [%1], 16, %2;"
                 :: "r"(dst), "l"(src), "r"(srcsize) : "memory");
}
#define CP_COMMIT asm volatile("cp.async.commit_group;" ::: "memory")
#define CP_WAIT(n) asm volatile("cp.async.wait_group %0;" :: "n"(n) : "memory")

__device__ __forceinline__ uint32_t pack_h2(float a, float b) {
    __half2 h = __floats2half2_rn(a, b);
    return *(uint32_t*)&h;
}
__device__ __forceinline__ void split_pair(float x0, float x1, uint32_t& hi, uint32_t& lo) {
    __half h0 = __float2half_rn(x0), h1 = __float2half_rn(x1);
    hi = pack_h2(__half2float(h0), __half2float(h1));
    lo = pack_h2(x0 - __half2float(h0), x1 - __half2float(h1));
}
__device__ __forceinline__ void mma16816(float* c, const uint32_t* a, const uint32_t* b) {
    asm volatile(
        "mma.sync.aligned.m16n8k16.row.col.f32.f16.f16.f32 "
        "{%0,%1,%2,%3}, {%4,%5,%6,%7}, {%8,%9}, {%0,%1,%2,%3};"
        : "+f"(c[0]), "+f"(c[1]), "+f"(c[2]), "+f"(c[3])
        : "r"(a[0]), "r"(a[1]), "r"(a[2]), "r"(a[3]), "r"(b[0]), "r"(b[1]));
}
// packed fp32x2 fma (Blackwell FFMA2)
__device__ __forceinline__ void fma2(float2& d, const float2& a, const float2& b) {
    asm("fma.rn.f32x2 %0, %1, %2, %0;"
        : "+l"(*(unsigned long long*)&d)
        : "l"(*(const unsigned long long*)&a), "l"(*(const unsigned long long*)&b));
}

// ---------------- conv1 (3->128, 3x3, s2, p1, relu) + FUSED prep/init tail blocks ----------------
// blocks [0,512): conv1; blocks [512,1088): weight prep (g_wB2/g_wt1B) + g_best init.
__global__ void k_conv1p(const float* __restrict__ x, const float* __restrict__ w,
                         const float* __restrict__ b,
                         const float* __restrict__ w2, const float* __restrict__ w1d) {
    int tid = threadIdx.x;
    if (blockIdx.x >= 512) {
        int pid = (blockIdx.x - 512) * 256 + tid;   // < 147456
        if (pid < 2048) g_best[pid] = 0xFFFFFFFFFFFFFFFFull;
        int j = pid & 3;
        int lane = (pid >> 2) & 31;
        int ni = (pid >> 7) & 7;
        int kc = (pid >> 10) & 1;
        int wn = (pid >> 11) & 1;
        int stage = pid >> 12;
        int lg = lane >> 2, lt = lane & 3;
        int oc = wn * 64 + ni * 8 + lg;
        int kloc = kc * 16 + 2 * lt + ((j & 1) ? 8 : 0);
        int cs = stage & 3;
        int c0 = cs * 32 + kloc;
        {
            int tap = stage >> 2;
            float w0 = w2[(oc * 128 + c0) * 9 + tap];
            float w1 = w2[(oc * 128 + c0 + 1) * 9 + tap];
            uint32_t hi, lo;
            split_pair(w0, w1, hi, lo);
            g_wB2[pid] = (j < 2) ? hi : lo;
        }
        {
            int t = stage >> 2;
            float w0 = w1d[(oc * 128 + c0) * 9 + t];
            float w1 = w1d[(oc * 128 + c0 + 1) * 9 + t];
            uint32_t hi, lo;
            split_pair(w0, w1, hi, lo);
            g_wt1B[pid] = (j < 2) ? hi : lo;
        }
        return;
    }
    __shared__ float2 sw2[64 * 27];
    __shared__ float sb[128];
    int id = blockIdx.x;
    int n = id >> 4, yt = (id >> 2) & 3, xt = id & 3;
    {
        float* swf = (float*)sw2;
        for (int i = tid; i < 3456; i += 256) {
            int oc = i / 27, k = i - oc * 27;
            swf[((oc >> 1) * 27 + k) * 2 + (oc & 1)] = w[i];
        }
    }
    if (tid < 128) sb[tid] = b[tid];
    int ox = xt * 16 + (tid & 15);
    int oy = yt * 16 + (tid >> 4);
    float2 iv2[27];
    const float* xb = x + n * 3 * 16384;
#pragma unroll
    for (int c = 0; c < 3; c++)
#pragma unroll
        for (int di = 0; di < 3; di++) {
            int gy = 2 * oy + di - 1;
#pragma unroll
            for (int dj = 0; dj < 3; dj++) {
                int gx = 2 * ox + dj - 1;
                float v = 0.f;
                if (gy >= 0 && gy < 128 && gx >= 0 && gx < 128)
                    v = xb[(c * 128 + gy) * 128 + gx];
                iv2[c * 9 + di * 3 + dj] = make_float2(v, v);
            }
        }
    __syncthreads();
    int pos64 = ((n * 64 + oy) * 64 + ox) * 64;
    uint4* dh = (uint4*)(g_h1h + pos64);
    uint4* dl = (uint4*)(g_h1l + pos64);
#pragma unroll 1
    for (int g8 = 0; g8 < 8; g8++) {
        float2 acc2[8];
#pragma unroll
        for (int l = 0; l < 8; l++)
            acc2[l] = make_float2(sb[g8 * 16 + 2 * l], sb[g8 * 16 + 2 * l + 1]);
#pragma unroll
        for (int k = 0; k < 27; k++) {
            float2 vv = iv2[k];
#pragma unroll
            for (int l = 0; l < 8; l++)
                fma2(acc2[l], sw2[(g8 * 8 + l) * 27 + k], vv);
        }
        uint32_t hw[8], lw[8];
#pragma unroll
        for (int l = 0; l < 8; l++) {
            float a0 = fmaxf(acc2[l].x, 0.f);
            float a1 = fmaxf(acc2[l].y, 0.f);
            split_pair(a0, a1, hw[l], lw[l]);
        }
        uint4 c0, c1;
        c0.x = hw[0]; c0.y = hw[4]; c0.z = hw[1]; c0.w = hw[5];
        c1.x = hw[2]; c1.y = hw[6]; c1.z = hw[3]; c1.w = hw[7];
        dh[g8 * 2] = c0; dh[g8 * 2 + 1] = c1;
        c0.x = lw[0]; c0.y = lw[4]; c0.z = lw[1]; c0.w = lw[5];
        c1.x = lw[2]; c1.y = lw[6]; c1.z = lw[3]; c1.w = lw[7];
        dl[g8 * 2] = c0; dl[g8 * 2 + 1] = c1;
    }
}

// ---------------- conv2 (fp16x2 mma, 3-pass) + pool + fused proj, triple-buffered ----------------
#define C2_AT 18432
#define C2_BT 16384
#define C2_BUFB (C2_AT + C2_BT)
#define C2_SP_OFF  16896
#define C2_PW_OFF  18000
#define C2_EPI_B ((C2_PW_OFF + 64 * 132) * 4)
#define C2_TRI_B (3 * C2_BUFB)
#define C2_SMEM ((C2_EPI_B > C2_TRI_B) ? C2_EPI_B : C2_TRI_B)

__global__ __launch_bounds__(256, 2) void k_conv2m(const float* __restrict__ b2,
                                                   const float* __restrict__ pw,
                                                   const float* __restrict__ pb,
                                                   float* __restrict__ dout, int wout) {
    extern __shared__ char sm[];
    uint32_t smb = smem_u32(sm);
    int tid = threadIdx.x;
    int warp = tid >> 5, lane = tid & 31;
    int wm = warp >> 1, wn = warp & 1;
    int lg = lane >> 2, lt = lane & 3;
    int bid = blockIdx.x;
    int n = bid >> 3, t = bid & 7;

    const uint32_t* asrc[4];
    uint32_t adst[4];
    bool y0[4], x0[4];
#pragma unroll
    for (int j = 0; j < 4; j++) {
        int c = j * 256 + tid;
        int m = c >> 3, q = c & 7;
        int kind = q >> 2, u = q & 3;
        int oy = t * 4 + (m >> 5), ox = m & 31;
        const uint32_t* gb = kind ? g_h1l : g_h1h;
        asrc[j] = gb + ((n * 64 + 2 * oy - 1) * 64 + (2 * ox - 1)) * 64 + u * 4;
        adst[j] = (uint32_t)(m * 144 + kind * 64 + u * 16);
        y0[j] = (oy == 0);
        x0[j] = (ox == 0);
    }
    const uint32_t* bsrc = g_wB2 + tid * 4;
    uint32_t bdst = (uint32_t)(C2_AT + tid * 16);

#define C2_LOAD(sidx)                                                            \
    do {                                                                         \
        int s_ = (sidx);                                                         \
        int tap_ = s_ >> 2, cs_ = s_ & 3;                                        \
        int di_ = tap_ / 3, dj_ = tap_ % 3;                                      \
        bool dy_ = (di_ > 0), dx_ = (dj_ > 0);                                   \
        int off_ = di_ * 4096 + dj_ * 64 + cs_ * 16;                             \
        uint32_t bb_ = smb + (uint32_t)((s_ % 3) * C2_BUFB);                     \
        _Pragma("unroll")                                                        \
        for (int j_ = 0; j_ < 4; j_++) {                                         \
            bool ok_ = (dy_ || !y0[j_]) && (dx_ || !x0[j_]);                     \
            cp16(bb_ + adst[j_], asrc[j_] + off_, ok_ ? 16u : 0u);               \
        }                                                                        \
        const uint32_t* bs_ = bsrc + s_ * 4096;                                  \
        _Pragma("unroll")                                                        \
        for (int j_ = 0; j_ < 4; j_++)                                           \
            cp16(bb_ + bdst + j_ * 4096, bs_ + j_ * 1024, 16u);                  \
        CP_COMMIT;                                                               \
    } while (0)

    float acc[2][8][4];
#pragma unroll
    for (int mi = 0; mi < 2; mi++)
#pragma unroll
        for (int ni = 0; ni < 8; ni++)
#pragma unroll
            for (int r = 0; r < 4; r++) acc[mi][ni][r] = 0.f;

    C2_LOAD(0);
    C2_LOAD(1);

    for (int s = 0; s < 36; s++) {
        if (s + 1 < 36) { CP_WAIT(1); } else { CP_WAIT(0); }
        __syncthreads();
        if (s + 2 < 36) C2_LOAD(s + 2);
        const uint32_t* As = (const uint32_t*)(sm + (s % 3) * C2_BUFB);
        const uint32_t* Bs = (const uint32_t*)(sm + (s % 3) * C2_BUFB + C2_AT);
#pragma unroll
        for (int kc = 0; kc < 2; kc++) {
            uint32_t ahi[2][4], alo[2][4];
#pragma unroll
            for (int mi = 0; mi < 2; mi++) {
                int r = wm * 32 + mi * 16 + lg;
                uint2 h0 = *(const uint2*)(As + r * 36 + kc * 8 + 2 * lt);
                uint2 h1 = *(const uint2*)(As + (r + 8) * 36 + kc * 8 + 2 * lt);
                uint2 l0 = *(const uint2*)(As + r * 36 + 16 + kc * 8 + 2 * lt);
                uint2 l1 = *(const uint2*)(As + (r + 8) * 36 + 16 + kc * 8 + 2 * lt);
                ahi[mi][0] = h0.x; ahi[mi][1] = h1.x; ahi[mi][2] = h0.y; ahi[mi][3] = h1.y;
                alo[mi][0] = l0.x; alo[mi][1] = l1.x; alo[mi][2] = l0.y; alo[mi][3] = l1.y;
            }
            uint32_t bh[8][2], bl[8][2];
#pragma unroll
            for (int ni = 0; ni < 8; ni++) {
                uint4 bv = *(const uint4*)(Bs + (((wn * 2 + kc) * 8 + ni) * 32 + lane) * 4);
                bh[ni][0] = bv.x; bh[ni][1] = bv.y;
                bl[ni][0] = bv.z; bl[ni][1] = bv.w;
            }
#pragma unroll
            for (int ni = 0; ni < 8; ni++)
#pragma unroll
                for (int mi = 0; mi < 2; mi++)
                    mma16816(acc[mi][ni], ahi[mi], bh[ni]);
#pragma unroll
            for (int ni = 0; ni < 8; ni++)
#pragma unroll
                for (int mi = 0; mi < 2; mi++)
                    mma16816(acc[mi][ni], alo[mi], bh[ni]);
#pragma unroll
            for (int ni = 0; ni < 8; ni++)
#pragma unroll
                for (int mi = 0; mi < 2; mi++)
                    mma16816(acc[mi][ni], ahi[mi], bl[ni]);
        }
    }
    __syncthreads();

    float* eb  = (float*)sm;
    float* sp  = (float*)sm + C2_SP_OFF;
    float* spw = (float*)sm + C2_PW_OFF;
#pragma unroll
    for (int mi = 0; mi < 2; mi++)
#pragma unroll
        for (int ni = 0; ni < 8; ni++) {
            int m = wm * 32 + mi * 16 + lg;
            int oc = wn * 64 + ni * 8 + 2 * lt;
            eb[m * 132 + oc]           = acc[mi][ni][0];
            eb[m * 132 + oc + 1]       = acc[mi][ni][1];
            eb[(m + 8) * 132 + oc]     = acc[mi][ni][2];
            eb[(m + 8) * 132 + oc + 1] = acc[mi][ni][3];
        }
    for (int i = tid; i < 64 * 32; i += 256) {
        int d = i >> 5, c4 = i & 31;
        float4 v = *(const float4*)(pw + d * 128 + c4 * 4);
        *(float4*)(spw + d * 132 + c4 * 4) = v;
    }
    __syncthreads();
    for (int i = tid; i < 1024; i += 256) {
        int pc = i >> 7, oc = i & 127;
        float bv = __ldg(&b2[oc]);
        float s = 0.f;
#pragma unroll
        for (int oyl = 0; oyl < 4; oyl++)
#pragma unroll
            for (int dx = 0; dx < 4; dx++) {
                int m = oyl * 32 + pc * 4 + dx;
                s += fmaxf(eb[m * 132 + oc] + bv, 0.f);
            }
        sp[pc * 132 + oc] = s * (1.f / 16.f);
    }
    __syncthreads();
#pragma unroll
    for (int j = 0; j < 2; j++) {
        int idx = j * 256 + tid;
        int pos = idx >> 6, d = idx & 63;
        float accz = __ldg(&pb[d]);
#pragma unroll 8
        for (int c4 = 0; c4 < 32; c4++) {
            float4 wv = *(const float4*)(spw + d * 132 + c4 * 4);
            float4 hv = *(const float4*)(sp + pos * 132 + c4 * 4);
            accz = fmaf(wv.x, hv.x, accz);
            accz = fmaf(wv.y, hv.y, accz);
            accz = fmaf(wv.z, hv.z, accz);
            accz = fmaf(wv.w, hv.w, accz);
        }
        int p = n * 64 + t * 8 + pos;
        g_ze[p * 64 + d] = accz;
        if (wout) dout[OFF_ZE + (n * 64 + d) * 64 + (t * 8 + pos)] = accz;
    }
}

// ---------------- vector quantizer: 256 codes per block, packed atomicMin ----------------
#define VQ_SMEMF (256 * 68 + 16 * 68 + 16 + 16 * 4 * 2)
__global__ __launch_bounds__(256) void k_vq(const float* __restrict__ cb) {
    extern __shared__ float smv[];
    float* scb = smv;
    float* szt = smv + 256 * 68;
    float* szn = szt + 16 * 68;
    float* red = szn + 16;
    int tid = threadIdx.x;
    int pg = blockIdx.x >> 1, half = blockIdx.x & 1;
    for (int i = tid; i < 256 * 16; i += 256) {
        int c = i >> 4, dd = i & 15;
        float4 v = *(const float4*)(cb + (half * 256 + c) * 64 + dd * 4);
        *(float4*)(scb + c * 68 + dd * 4) = v;
    }
    for (int i = tid; i < 16 * 16; i += 256) {
        int p = i >> 4, dd = i & 15;
        float4 v = *(const float4*)(g_ze + (pg * 16 + p) * 64 + dd * 4);
        *(float4*)(szt + p * 68 + dd * 4) = v;
    }
    __syncthreads();
    if (tid < 16) {
        float s = 0.f;
#pragma unroll 8
        for (int d = 0; d < 64; d++) { float z = szt[tid * 68 + d]; s = fmaf(z, z, s); }
        szn[tid] = s;
    }
    __syncthreads();
    int warp = tid >> 5, lane = tid & 31;
    int q = warp & 3, h = warp >> 2;

    float dot[2][8], csq[2];
#pragma unroll
    for (int i = 0; i < 2; i++) {
        csq[i] = 0.f;
#pragma unroll
        for (int p = 0; p < 8; p++) dot[i][p] = 0.f;
    }
#pragma unroll 2
    for (int d4 = 0; d4 < 16; d4++) {
        float4 zz[8];
#pragma unroll
        for (int p = 0; p < 8; p++)
            zz[p] = *(const float4*)(szt + (h * 8 + p) * 68 + d4 * 4);
#pragma unroll
        for (int i = 0; i < 2; i++) {
            float4 cc = *(const float4*)(scb + (q * 64 + lane + i * 32) * 68 + d4 * 4);
            csq[i] = fmaf(cc.x, cc.x, csq[i]);
            csq[i] = fmaf(cc.y, cc.y, csq[i]);
            csq[i] = fmaf(cc.z, cc.z, csq[i]);
            csq[i] = fmaf(cc.w, cc.w, csq[i]);
#pragma unroll
            for (int p = 0; p < 8; p++) {
                float tt = dot[i][p];
                tt = fmaf(cc.x, zz[p].x, tt);
                tt = fmaf(cc.y, zz[p].y, tt);
                tt = fmaf(cc.z, zz[p].z, tt);
                tt = fmaf(cc.w, zz[p].w, tt);
                dot[i][p] = tt;
            }
        }
    }
#pragma unroll
    for (int p = 0; p < 8; p++) {
        float zn = szn[h * 8 + p];
        float bd = 3.4e38f; int bi = 0;
#pragma unroll
        for (int i = 0; i < 2; i++) {
            float dist = zn + csq[i] - 2.f * dot[i][p];
            int idx = half * 256 + q * 64 + lane + i * 32;
            if (dist < bd) { bd = dist; bi = idx; }
        }
#pragma unroll
        for (int off = 16; off > 0; off >>= 1) {
            float od = __shfl_down_sync(0xffffffffu, bd, off);
            int   oi = __shfl_down_sync(0xffffffffu, bi, off);
            if (od < bd || (od == bd && oi < bi)) { bd = od; bi = oi; }
        }
        if (lane == 0) {
            red[((h * 8 + p) * 4 + q) * 2]     = bd;
            red[((h * 8 + p) * 4 + q) * 2 + 1] = __int_as_float(bi);
        }
    }
    __syncthreads();
    if (tid < 16) {
        float bd = 3.4e38f; int bi = 0;
#pragma unroll
        for (int qq = 0; qq < 4; qq++) {
            float od = red[(tid * 4 + qq) * 2];
            int   oi = __float_as_int(red[(tid * 4 + qq) * 2 + 1]);
            if (od < bd || (od == bd && oi < bi)) { bd = od; bi = oi; }
        }
        unsigned long long key = (((unsigned long long)__float_as_uint(bd)) << 32)
                               | (unsigned long long)(unsigned)bi;
        atomicMin(&g_best[pg * 16 + tid], key);
    }
}

// ---------------- decoder 1x1 dproj + relu -> split/packed/permuted g_rh/g_rl ----------------
__global__ void k_dec_r(const float* __restrict__ cb, const float* __restrict__ dpw,
                        const float* __restrict__ dpb) {
    __shared__ float sdw[128 * 65];
    __shared__ float scr[8][64];
    __shared__ float srr[8][128];
    int tid = threadIdx.x;
    for (int i = tid; i < 128 * 64; i += 128) {
        int c = i >> 6, d = i & 63;
        sdw[c * 65 + d] = dpw[i];
    }
    for (int i = tid; i < 8 * 64; i += 128) {
        int pl = i >> 6, d = i & 63;
        int p = blockIdx.x * 8 + pl;
        int idx = (int)(g_best[p] & 0xFFFFFFFFull);
        scr[pl][d] = cb[idx * 64 + d];
    }
    __syncthreads();
    int c = tid;
    float bv = dpb[c];
    for (int pl = 0; pl < 8; pl++) {
        float acc = bv;
#pragma unroll 4
        for (int d = 0; d < 64; d++) acc = fmaf(sdw[c * 65 + d], scr[pl][d], acc);
        srr[pl][c] = fmaxf(acc, 0.f);
    }
    __syncthreads();
    for (int i = tid; i < 8 * 64; i += 128) {
        int pl = i >> 6, pr = i & 63;
        float x0 = srr[pl][2 * pr], x1 = srr[pl][2 * pr + 1];
        uint32_t hi, lo;
        split_pair(x0, x1, hi, lo);
        int blk = pr >> 3, ii = pr & 7;
        int pos = blk * 8 + ((ii < 4) ? 2 * ii : 2 * ii - 7);
        int p = blockIdx.x * 8 + pl;
        g_rh[p * 64 + pos] = hi;
        g_rl[p * 64 + pos] = lo;
    }
}

// ---------------- q = r @ wt1 per tap, tensor fp16x2 (double-buffered, 3-pass) ----------------
#define QM_SMEM_MAIN (2 * C2_BUFB)
__device__ __forceinline__ void qm_load_stage(uint32_t smb, int buf, int s,
                                              int gt, int t, int tid) {
    uint32_t bb = smb + buf * C2_BUFB;
#pragma unroll
    for (int j = 0; j < 4; j++) {
        int c = j * 256 + tid;
        int m = c >> 3, q = c & 7;
        int kind = q >> 2, u = q & 3;
        const uint32_t* gbase = kind ? g_rl : g_rh;
        cp16(bb + m * 144 + kind * 64 + u * 16,
             gbase + (gt * 128 + m) * 64 + s * 16 + u * 4, 16u);
    }
#pragma unroll
    for (int j = 0; j < 4; j++) {
        int c = j * 256 + tid;
        cp16(bb + C2_AT + c * 16, g_wt1B + (t * 4 + s) * 4096 + c * 4, 16u);
    }
    CP_COMMIT;
}

__global__ __launch_bounds__(256, 2) void k_qm() {
    extern __shared__ char sm[];
    uint32_t smb = smem_u32(sm);
    int tid = threadIdx.x;
    int warp = tid >> 5, lane = tid & 31;
    int wm = warp >> 1, wn = warp & 1;
    int lg = lane >> 2, lt = lane & 3;
    int gt = blockIdx.x, t = blockIdx.y;

    float acc[2][8][4];
#pragma unroll
    for (int mi = 0; mi < 2; mi++)
#pragma unroll
        for (int ni = 0; ni < 8; ni++)
#pragma unroll
            for (int r = 0; r < 4; r++) acc[mi][ni][r] = 0.f;

    qm_load_stage(smb, 0, 0, gt, t, tid);
    for (int s = 0; s < 4; s++) {
        int buf = s & 1;
        if (s + 1 < 4) qm_load_stage(smb, buf ^ 1, s + 1, gt, t, tid);
        if (s + 1 < 4) { CP_WAIT(1); } else { CP_WAIT(0); }
        __syncthreads();
        const uint32_t* As = (const uint32_t*)(sm + buf * C2_BUFB);
        const uint32_t* Bs = (const uint32_t*)(sm + buf * C2_BUFB + C2_AT);
#pragma unroll
        for (int kc = 0; kc < 2; kc++) {
            uint32_t ahi[2][4], alo[2][4];
#pragma unroll
            for (int mi = 0; mi < 2; mi++) {
                int r = wm * 32 + mi * 16 + lg;
                uint2 h0 = *(const uint2*)(As + r * 36 + kc * 8 + 2 * lt);
                uint2 h1 = *(const uint2*)(As + (r + 8) * 36 + kc * 8 + 2 * lt);
                uint2 l0 = *(const uint2*)(As + r * 36 + 16 + kc * 8 + 2 * lt);
                uint2 l1 = *(const uint2*)(As + (r + 8) * 36 + 16 + kc * 8 + 2 * lt);
                ahi[mi][0] = h0.x; ahi[mi][1] = h1.x; ahi[mi][2] = h0.y; ahi[mi][3] = h1.y;
                alo[mi][0] = l0.x; alo[mi][1] = l1.x; alo[mi][2] = l0.y; alo[mi][3] = l1.y;
            }
            uint32_t bh[8][2], bl[8][2];
#pragma unroll
            for (int ni = 0; ni < 8; ni++) {
                uint4 bv = *(const uint4*)(Bs + (((wn * 2 + kc) * 8 + ni) * 32 + lane) * 4);
                bh[ni][0] = bv.x; bh[ni][1] = bv.y;
                bl[ni][0] = bv.z; bl[ni][1] = bv.w;
            }
#pragma unroll
            for (int ni = 0; ni < 8; ni++)
#pragma unroll
                for (int mi = 0; mi < 2; mi++)
                    mma16816(acc[mi][ni], ahi[mi], bh[ni]);
#pragma unroll
            for (int ni = 0; ni < 8; ni++)
#pragma unroll
                for (int mi = 0; mi < 2; mi++)
                    mma16816(acc[mi][ni], alo[mi], bh[ni]);
#pragma unroll
            for (int ni = 0; ni < 8; ni++)
#pragma unroll
                for (int mi = 0; mi < 2; mi++)
                    mma16816(acc[mi][ni], ahi[mi], bl[ni]);
        }
        __syncthreads();
    }
    float* eb = (float*)sm;
#pragma unroll
    for (int mi = 0; mi < 2; mi++)
#pragma unroll
        for (int ni = 0; ni < 8; ni++) {
            int m = wm * 32 + mi * 16 + lg;
            int oc = wn * 64 + ni * 8 + 2 * lt;
            eb[m * 132 + oc]           = acc[mi][ni][0];
            eb[m * 132 + oc + 1]       = acc[mi][ni][1];
            eb[(m + 8) * 132 + oc]     = acc[mi][ni][2];
            eb[(m + 8) * 132 + oc + 1] = acc[mi][ni][3];
        }
    __syncthreads();
    for (int i = tid; i < 4096; i += 256) {
        int m = i >> 5, o4 = i & 31;
        float4 v;
        v.x = eb[m * 132 + o4 * 4];
        v.y = eb[m * 132 + o4 * 4 + 1];
        v.z = eb[m * 132 + o4 * 4 + 2];
        v.w = eb[m * 132 + o4 * 4 + 3];
        *(float4*)(g_q + (t * 2048 + gt * 128 + m) * 128 + o4 * 4) = v;
    }
}

// ---------------- per-block pixel types + FUSED x_hat scatter + idx/loss tail ----------------
// grid: [0,2048) xblk blocks; [2048,2064) idx tail (128 thr each); 2064 loss block.
__global__ void k_xblk(const float* __restrict__ b1d, const float* __restrict__ dw2,
                       const float* __restrict__ db2, float* __restrict__ dout, int wout) {
    if (blockIdx.x >= 2048) {
        if (!wout) return;
        int tid = threadIdx.x;
        if (blockIdx.x < 2064) {
            int fid = (blockIdx.x - 2048) * 128 + tid;
            dout[OFF_IDX + fid] = (float)(unsigned)(g_best[fid] & 0xFFFFFFFFull);
        } else {
            __shared__ float sred[128];
            float s = 0.f;
#pragma unroll
            for (int k = 0; k < 16; k++) {
                int p = k * 128 + tid;
                s += __uint_as_float((unsigned)(g_best[p] >> 32));
            }
            sred[tid] = s;
            __syncthreads();
            for (int off = 64; off > 0; off >>= 1) {
                if (tid < off) sred[tid] += sred[tid + off];
                __syncthreads();
            }
            if (tid == 0) dout[OFF_LOSS] = 1.25f * sred[0] * (1.0f / 131072.0f);
        }
        return;
    }
    __shared__ float sz[9 * 132];
    __shared__ float sxo[27];
    __shared__ float sw2[3 * 128];
    int g = blockIdx.x;
    int n = g >> 6, bi = (g >> 3) & 7, bj = g & 7;
    int o = threadIdx.x;
    for (int i = o; i < 384; i += 128) sw2[i] = dw2[i];
    float bo = b1d[o];
    float s[3][3];
#pragma unroll
    for (int ti = 0; ti < 3; ti++)
#pragma unroll
        for (int tj = 0; tj < 3; tj++) s[ti][tj] = bo;
    const int OFF[3][2]  = {{-1, 0}, {0, 0}, {1, 0}};
    const int MSK[3][2]  = {{1, 6}, {7, 0}, {4, 3}};
#pragma unroll
    for (int di = 0; di < 3; di++)
#pragma unroll
        for (int dj = 0; dj < 3; dj++) {
            const float* qb = g_q + ((di * 3 + dj) * 2048 + n * 64) * 128 + o;
#pragma unroll
            for (int a = 0; a < 2; a++) {
                int tim = MSK[di][a];
                if (tim == 0) continue;
                int roff = OFF[di][a];
                int bi2 = bi + roff;
#pragma unroll
                for (int bb = 0; bb < 2; bb++) {
                    int tjm = MSK[dj][bb];
                    if (tjm == 0) continue;
                    int coff = OFF[dj][bb];
                    int bj2 = bj + coff;
                    float v = 0.f;
                    if (bi2 >= 0 && bi2 < 8 && bj2 >= 0 && bj2 < 8)
                        v = qb[(bi2 * 8 + bj2) * 128];
#pragma unroll
                    for (int ti = 0; ti < 3; ti++)
                        if ((tim >> ti) & 1)
#pragma unroll
                            for (int tj = 0; tj < 3; tj++)
                                if ((tjm >> tj) & 1) s[ti][tj] += v;
                }
            }
        }
#pragma unroll
    for (int ti = 0; ti < 3; ti++)
#pragma unroll
        for (int tj = 0; tj < 3; tj++)
            sz[(ti * 3 + tj) * 132 + o] = fmaxf(s[ti][tj], 0.f);
    __syncthreads();
    if (o < 27) {
        int ty = o / 3, co = o % 3;
        float acc = db2[co];
#pragma unroll 4
        for (int c = 0; c < 128; c++)
            acc = fmaf(sw2[co * 128 + c], sz[ty * 132 + c], acc);
        sxo[ty * 3 + co] = acc;
    }
    __syncthreads();
    float* xb = dout + ((size_t)n * 3) * 16384 + (bi * 16) * 128 + bj * 16;
    for (int e = o; e < 768; e += 128) {
        int j = e & 15, i2 = (e >> 4) & 15, c = e >> 8;
        int ti = (i2 == 0) ? 0 : ((i2 == 15) ? 2 : 1);
        int tj = (j == 0) ? 0 : ((j == 15) ? 2 : 1);
        xb[(c * 128 + i2) * 128 + j] = sxo[(ti * 3 + tj) * 3 + c];
    }
}

// ---------------- launcher ----------------
extern "C" void kernel_launch(void* const* d_in, const int* in_sizes, int n_in,
                              void* d_out, int out_size) {
    const float* x   = (const float*)d_in[0];
    const float* w1  = (const float*)d_in[1];
    const float* b1  = (const float*)d_in[2];
    const float* w2  = (const float*)d_in[3];
    const float* b2  = (const float*)d_in[4];
    const float* pw  = (const float*)d_in[5];
    const float* pb  = (const float*)d_in[6];
    const float* cb  = (const float*)d_in[7];
    const float* dpw = (const float*)d_in[8];
    const float* dpb = (const float*)d_in[9];
    const float* w1d = (const float*)d_in[10];
    const float* b1d = (const float*)d_in[11];
    const float* dw2 = (const float*)d_in[12];
    const float* db2 = (const float*)d_in[13];
    float* out = (float*)d_out;

    cudaFuncSetAttribute(k_conv2m, cudaFuncAttributeMaxDynamicSharedMemorySize, C2_SMEM);
    cudaFuncSetAttribute(k_qm, cudaFuncAttributeMaxDynamicSharedMemorySize, QM_SMEM_MAIN);
    cudaFuncSetAttribute(k_vq, cudaFuncAttributeMaxDynamicSharedMemorySize, VQ_SMEMF * 4);

    int wout = (out_size >= OUT_FULL) ? 1 : 0;

    k_conv1p<<<1088, 256>>>(x, w1, b1, w2, w1d);            // 1 (conv1 + prep + init)
    k_conv2m<<<256, 256, C2_SMEM>>>(b2, pw, pb, out, wout); // 2
    k_vq<<<256, 256, VQ_SMEMF * 4>>>(cb);                   // 3
    k_dec_r<<<256, 128>>>(cb, dpw, dpb);                    // 4  <- profiled
    k_qm<<<dim3(16, 9), 256, QM_SMEM_MAIN>>>();             // 5
    k_xblk<<<2065, 128>>>(b1d, dw2, db2, out, wout);        // 6
}

// round 17
// speedup vs baseline: 1.0644x; 1.0278x over previous
#include <cuda_runtime.h>
#include <cuda_fp16.h>
#include <cstdint>

// ---------------- constants ----------------
#define OFF_IDX   1572864
#define OFF_LOSS  1574912
#define OFF_ZE    1574913
#define OUT_FULL  1705985

// ---------------- scratch (device globals) ----------------
__device__ uint32_t g_h1h[32 * 64 * 64 * 64];
__device__ uint32_t g_h1l[32 * 64 * 64 * 64];
__device__ float g_ze[2048 * 64];
__device__ unsigned long long g_best[2048];
__device__ uint32_t g_rh[2048 * 64];
__device__ uint32_t g_rl[2048 * 64];
__device__ float g_q[9 * 2048 * 128];
__device__ uint32_t g_wB2[36 * 4096];
__device__ uint32_t g_wt1B[36 * 4096];

// ---------------- PTX helpers ----------------
__device__ __forceinline__ uint32_t smem_u32(const void* p) {
    uint32_t a;
    asm("{ .reg .u64 t; cvta.to.shared.u64 t, %1; cvt.u32.u64 %0, t; }" : "=r"(a) : "l"(p));
    return a;
}
__device__ __forceinline__ void cp16(uint32_t dst, const void* src, uint32_t srcsize) {
    asm volatile("cp.async.cg.shared.global [%0], [%1], 16, %2;"
                 :: "r"(dst), "l"(src), "r"(srcsize) : "memory");
}
#define CP_COMMIT asm volatile("cp.async.commit_group;" ::: "memory")
#define CP_WAIT(n) asm volatile("cp.async.wait_group %0;" :: "n"(n) : "memory")

__device__ __forceinline__ uint32_t pack_h2(float a, float b) {
    __half2 h = __floats2half2_rn(a, b);
    return *(uint32_t*)&h;
}
__device__ __forceinline__ void split_pair(float x0, float x1, uint32_t& hi, uint32_t& lo) {
    __half h0 = __float2half_rn(x0), h1 = __float2half_rn(x1);
    hi = pack_h2(__half2float(h0), __half2float(h1));
    lo = pack_h2(x0 - __half2float(h0), x1 - __half2float(h1));
}
__device__ __forceinline__ void mma16816(float* c, const uint32_t* a, const uint32_t* b) {
    asm volatile(
        "mma.sync.aligned.m16n8k16.row.col.f32.f16.f16.f32 "
        "{%0,%1,%2,%3}, {%4,%5,%6,%7}, {%8,%9}, {%0,%1,%2,%3};"
        : "+f"(c[0]), "+f"(c[1]), "+f"(c[2]), "+f"(c[3])
        : "r"(a[0]), "r"(a[1]), "r"(a[2]), "r"(a[3]), "r"(b[0]), "r"(b[1]));
}
// packed fp32x2 fma (Blackwell FFMA2)
__device__ __forceinline__ void fma2(float2& d, const float2& a, const float2& b) {
    asm("fma.rn.f32x2 %0, %1, %2, %0;"
        : "+l"(*(unsigned long long*)&d)
        : "l"(*(const unsigned long long*)&a), "l"(*(const unsigned long long*)&b));
}

// ---------------- conv1 (3->128, 3x3, s2, p1, relu) + FUSED prep/init tail blocks ----------------
// blocks [0,512): conv1; blocks [512,1088): weight prep (g_wB2/g_wt1B) + g_best init.
__global__ void k_conv1p(const float* __restrict__ x, const float* __restrict__ w,
                         const float* __restrict__ b,
                         const float* __restrict__ w2, const float* __restrict__ w1d) {
    int tid = threadIdx.x;
    if (blockIdx.x >= 512) {
        int pid = (blockIdx.x - 512) * 256 + tid;   // < 147456
        if (pid < 2048) g_best[pid] = 0xFFFFFFFFFFFFFFFFull;
        int j = pid & 3;
        int lane = (pid >> 2) & 31;
        int ni = (pid >> 7) & 7;
        int kc = (pid >> 10) & 1;
        int wn = (pid >> 11) & 1;
        int stage = pid >> 12;
        int lg = lane >> 2, lt = lane & 3;
        int oc = wn * 64 + ni * 8 + lg;
        int kloc = kc * 16 + 2 * lt + ((j & 1) ? 8 : 0);
        int cs = stage & 3;
        int c0 = cs * 32 + kloc;
        {
            int tap = stage >> 2;
            float w0 = w2[(oc * 128 + c0) * 9 + tap];
            float w1 = w2[(oc * 128 + c0 + 1) * 9 + tap];
            uint32_t hi, lo;
            split_pair(w0, w1, hi, lo);
            g_wB2[pid] = (j < 2) ? hi : lo;
        }
        {
            int t = stage >> 2;
            float w0 = w1d[(oc * 128 + c0) * 9 + t];
            float w1 = w1d[(oc * 128 + c0 + 1) * 9 + t];
            uint32_t hi, lo;
            split_pair(w0, w1, hi, lo);
            g_wt1B[pid] = (j < 2) ? hi : lo;
        }
        return;
    }
    __shared__ float2 sw2[64 * 27];
    __shared__ float sb[128];
    int id = blockIdx.x;
    int n = id >> 4, yt = (id >> 2) & 3, xt = id & 3;
    {
        float* swf = (float*)sw2;
        for (int i = tid; i < 3456; i += 256) {
            int oc = i / 27, k = i - oc * 27;
            swf[((oc >> 1) * 27 + k) * 2 + (oc & 1)] = w[i];
        }
    }
    if (tid < 128) sb[tid] = b[tid];
    int ox = xt * 16 + (tid & 15);
    int oy = yt * 16 + (tid >> 4);
    float2 iv2[27];
    const float* xb = x + n * 3 * 16384;
#pragma unroll
    for (int c = 0; c < 3; c++)
#pragma unroll
        for (int di = 0; di < 3; di++) {
            int gy = 2 * oy + di - 1;
#pragma unroll
            for (int dj = 0; dj < 3; dj++) {
                int gx = 2 * ox + dj - 1;
                float v = 0.f;
                if (gy >= 0 && gy < 128 && gx >= 0 && gx < 128)
                    v = xb[(c * 128 + gy) * 128 + gx];
                iv2[c * 9 + di * 3 + dj] = make_float2(v, v);
            }
        }
    __syncthreads();
    int pos64 = ((n * 64 + oy) * 64 + ox) * 64;
    uint4* dh = (uint4*)(g_h1h + pos64);
    uint4* dl = (uint4*)(g_h1l + pos64);
#pragma unroll 1
    for (int g8 = 0; g8 < 8; g8++) {
        float2 acc2[8];
#pragma unroll
        for (int l = 0; l < 8; l++)
            acc2[l] = make_float2(sb[g8 * 16 + 2 * l], sb[g8 * 16 + 2 * l + 1]);
#pragma unroll
        for (int k = 0; k < 27; k++) {
            float2 vv = iv2[k];
#pragma unroll
            for (int l = 0; l < 8; l++)
                fma2(acc2[l], sw2[(g8 * 8 + l) * 27 + k], vv);
        }
        uint32_t hw[8], lw[8];
#pragma unroll
        for (int l = 0; l < 8; l++) {
            float a0 = fmaxf(acc2[l].x, 0.f);
            float a1 = fmaxf(acc2[l].y, 0.f);
            split_pair(a0, a1, hw[l], lw[l]);
        }
        uint4 c0, c1;
        c0.x = hw[0]; c0.y = hw[4]; c0.z = hw[1]; c0.w = hw[5];
        c1.x = hw[2]; c1.y = hw[6]; c1.z = hw[3]; c1.w = hw[7];
        dh[g8 * 2] = c0; dh[g8 * 2 + 1] = c1;
        c0.x = lw[0]; c0.y = lw[4]; c0.z = lw[1]; c0.w = lw[5];
        c1.x = lw[2]; c1.y = lw[6]; c1.z = lw[3]; c1.w = lw[7];
        dl[g8 * 2] = c0; dl[g8 * 2 + 1] = c1;
    }
}

// ---------------- conv2 (fp16x2 mma, 3-pass) + pool + fused proj, triple-buffered ----------------
#define C2_AT 18432
#define C2_BT 16384
#define C2_BUFB (C2_AT + C2_BT)
#define C2_SP_OFF  16896
#define C2_PW_OFF  18000
#define C2_EPI_B ((C2_PW_OFF + 64 * 132) * 4)
#define C2_TRI_B (3 * C2_BUFB)
#define C2_SMEM ((C2_EPI_B > C2_TRI_B) ? C2_EPI_B : C2_TRI_B)

__global__ __launch_bounds__(256, 2) void k_conv2m(const float* __restrict__ b2,
                                                   const float* __restrict__ pw,
                                                   const float* __restrict__ pb,
                                                   float* __restrict__ dout, int wout) {
    extern __shared__ char sm[];
    uint32_t smb = smem_u32(sm);
    int tid = threadIdx.x;
    int warp = tid >> 5, lane = tid & 31;
    int wm = warp >> 1, wn = warp & 1;
    int lg = lane >> 2, lt = lane & 3;
    int bid = blockIdx.x;
    int n = bid >> 3, t = bid & 7;

    const uint32_t* asrc[4];
    uint32_t adst[4];
    bool y0[4], x0[4];
#pragma unroll
    for (int j = 0; j < 4; j++) {
        int c = j * 256 + tid;
        int m = c >> 3, q = c & 7;
        int kind = q >> 2, u = q & 3;
        int oy = t * 4 + (m >> 5), ox = m & 31;
        const uint32_t* gb = kind ? g_h1l : g_h1h;
        asrc[j] = gb + ((n * 64 + 2 * oy - 1) * 64 + (2 * ox - 1)) * 64 + u * 4;
        adst[j] = (uint32_t)(m * 144 + kind * 64 + u * 16);
        y0[j] = (oy == 0);
        x0[j] = (ox == 0);
    }
    const uint32_t* bsrc = g_wB2 + tid * 4;
    uint32_t bdst = (uint32_t)(C2_AT + tid * 16);

#define C2_LOAD(sidx)                                                            \
    do {                                                                         \
        int s_ = (sidx);                                                         \
        int tap_ = s_ >> 2, cs_ = s_ & 3;                                        \
        int di_ = tap_ / 3, dj_ = tap_ % 3;                                      \
        bool dy_ = (di_ > 0), dx_ = (dj_ > 0);                                   \
        int off_ = di_ * 4096 + dj_ * 64 + cs_ * 16;                             \
        uint32_t bb_ = smb + (uint32_t)((s_ % 3) * C2_BUFB);                     \
        _Pragma("unroll")                                                        \
        for (int j_ = 0; j_ < 4; j_++) {                                         \
            bool ok_ = (dy_ || !y0[j_]) && (dx_ || !x0[j_]);                     \
            cp16(bb_ + adst[j_], asrc[j_] + off_, ok_ ? 16u : 0u);               \
        }                                                                        \
        const uint32_t* bs_ = bsrc + s_ * 4096;                                  \
        _Pragma("unroll")                                                        \
        for (int j_ = 0; j_ < 4; j_++)                                           \
            cp16(bb_ + bdst + j_ * 4096, bs_ + j_ * 1024, 16u);                  \
        CP_COMMIT;                                                               \
    } while (0)

    float acc[2][8][4];
#pragma unroll
    for (int mi = 0; mi < 2; mi++)
#pragma unroll
        for (int ni = 0; ni < 8; ni++)
#pragma unroll
            for (int r = 0; r < 4; r++) acc[mi][ni][r] = 0.f;

    C2_LOAD(0);
    C2_LOAD(1);

    for (int s = 0; s < 36; s++) {
        if (s + 1 < 36) { CP_WAIT(1); } else { CP_WAIT(0); }
        __syncthreads();
        if (s + 2 < 36) C2_LOAD(s + 2);
        const uint32_t* As = (const uint32_t*)(sm + (s % 3) * C2_BUFB);
        const uint32_t* Bs = (const uint32_t*)(sm + (s % 3) * C2_BUFB + C2_AT);
#pragma unroll
        for (int kc = 0; kc < 2; kc++) {
            uint32_t ahi[2][4], alo[2][4];
#pragma unroll
            for (int mi = 0; mi < 2; mi++) {
                int r = wm * 32 + mi * 16 + lg;
                uint2 h0 = *(const uint2*)(As + r * 36 + kc * 8 + 2 * lt);
                uint2 h1 = *(const uint2*)(As + (r + 8) * 36 + kc * 8 + 2 * lt);
                uint2 l0 = *(const uint2*)(As + r * 36 + 16 + kc * 8 + 2 * lt);
                uint2 l1 = *(const uint2*)(As + (r + 8) * 36 + 16 + kc * 8 + 2 * lt);
                ahi[mi][0] = h0.x; ahi[mi][1] = h1.x; ahi[mi][2] = h0.y; ahi[mi][3] = h1.y;
                alo[mi][0] = l0.x; alo[mi][1] = l1.x; alo[mi][2] = l0.y; alo[mi][3] = l1.y;
            }
            uint32_t bh[8][2], bl[8][2];
#pragma unroll
            for (int ni = 0; ni < 8; ni++) {
                uint4 bv = *(const uint4*)(Bs + (((wn * 2 + kc) * 8 + ni) * 32 + lane) * 4);
                bh[ni][0] = bv.x; bh[ni][1] = bv.y;
                bl[ni][0] = bv.z; bl[ni][1] = bv.w;
            }
#pragma unroll
            for (int ni = 0; ni < 8; ni++)
#pragma unroll
                for (int mi = 0; mi < 2; mi++)
                    mma16816(acc[mi][ni], ahi[mi], bh[ni]);
#pragma unroll
            for (int ni = 0; ni < 8; ni++)
#pragma unroll
                for (int mi = 0; mi < 2; mi++)
                    mma16816(acc[mi][ni], alo[mi], bh[ni]);
#pragma unroll
            for (int ni = 0; ni < 8; ni++)
#pragma unroll
                for (int mi = 0; mi < 2; mi++)
                    mma16816(acc[mi][ni], ahi[mi], bl[ni]);
        }
    }
    __syncthreads();

    float* eb  = (float*)sm;
    float* sp  = (float*)sm + C2_SP_OFF;
    float* spw = (float*)sm + C2_PW_OFF;
#pragma unroll
    for (int mi = 0; mi < 2; mi++)
#pragma unroll
        for (int ni = 0; ni < 8; ni++) {
            int m = wm * 32 + mi * 16 + lg;
            int oc = wn * 64 + ni * 8 + 2 * lt;
            eb[m * 132 + oc]           = acc[mi][ni][0];
            eb[m * 132 + oc + 1]       = acc[mi][ni][1];
            eb[(m + 8) * 132 + oc]     = acc[mi][ni][2];
            eb[(m + 8) * 132 + oc + 1] = acc[mi][ni][3];
        }
    for (int i = tid; i < 64 * 32; i += 256) {
        int d = i >> 5, c4 = i & 31;
        float4 v = *(const float4*)(pw + d * 128 + c4 * 4);
        *(float4*)(spw + d * 132 + c4 * 4) = v;
    }
    __syncthreads();
    for (int i = tid; i < 1024; i += 256) {
        int pc = i >> 7, oc = i & 127;
        float bv = __ldg(&b2[oc]);
        float s = 0.f;
#pragma unroll
        for (int oyl = 0; oyl < 4; oyl++)
#pragma unroll
            for (int dx = 0; dx < 4; dx++) {
                int m = oyl * 32 + pc * 4 + dx;
                s += fmaxf(eb[m * 132 + oc] + bv, 0.f);
            }
        sp[pc * 132 + oc] = s * (1.f / 16.f);
    }
    __syncthreads();
#pragma unroll
    for (int j = 0; j < 2; j++) {
        int idx = j * 256 + tid;
        int pos = idx >> 6, d = idx & 63;
        float accz = __ldg(&pb[d]);
#pragma unroll 8
        for (int c4 = 0; c4 < 32; c4++) {
            float4 wv = *(const float4*)(spw + d * 132 + c4 * 4);
            float4 hv = *(const float4*)(sp + pos * 132 + c4 * 4);
            accz = fmaf(wv.x, hv.x, accz);
            accz = fmaf(wv.y, hv.y, accz);
            accz = fmaf(wv.z, hv.z, accz);
            accz = fmaf(wv.w, hv.w, accz);
        }
        int p = n * 64 + t * 8 + pos;
        g_ze[p * 64 + d] = accz;
        if (wout) dout[OFF_ZE + (n * 64 + d) * 64 + (t * 8 + pos)] = accz;
    }
}

// ---------------- vector quantizer: 256 codes per block, packed atomicMin ----------------
#define VQ_SMEMF (256 * 68 + 16 * 68 + 16 + 16 * 4 * 2)
__global__ __launch_bounds__(256) void k_vq(const float* __restrict__ cb) {
    extern __shared__ float smv[];
    float* scb = smv;
    float* szt = smv + 256 * 68;
    float* szn = szt + 16 * 68;
    float* red = szn + 16;
    int tid = threadIdx.x;
    int pg = blockIdx.x >> 1, half = blockIdx.x & 1;
    for (int i = tid; i < 256 * 16; i += 256) {
        int c = i >> 4, dd = i & 15;
        float4 v = *(const float4*)(cb + (half * 256 + c) * 64 + dd * 4);
        *(float4*)(scb + c * 68 + dd * 4) = v;
    }
    for (int i = tid; i < 16 * 16; i += 256) {
        int p = i >> 4, dd = i & 15;
        float4 v = *(const float4*)(g_ze + (pg * 16 + p) * 64 + dd * 4);
        *(float4*)(szt + p * 68 + dd * 4) = v;
    }
    __syncthreads();
    if (tid < 16) {
        float s = 0.f;
#pragma unroll 8
        for (int d = 0; d < 64; d++) { float z = szt[tid * 68 + d]; s = fmaf(z, z, s); }
        szn[tid] = s;
    }
    __syncthreads();
    int warp = tid >> 5, lane = tid & 31;
    int q = warp & 3, h = warp >> 2;

    float dot[2][8], csq[2];
#pragma unroll
    for (int i = 0; i < 2; i++) {
        csq[i] = 0.f;
#pragma unroll
        for (int p = 0; p < 8; p++) dot[i][p] = 0.f;
    }
#pragma unroll 2
    for (int d4 = 0; d4 < 16; d4++) {
        float4 zz[8];
#pragma unroll
        for (int p = 0; p < 8; p++)
            zz[p] = *(const float4*)(szt + (h * 8 + p) * 68 + d4 * 4);
#pragma unroll
        for (int i = 0; i < 2; i++) {
            float4 cc = *(const float4*)(scb + (q * 64 + lane + i * 32) * 68 + d4 * 4);
            csq[i] = fmaf(cc.x, cc.x, csq[i]);
            csq[i] = fmaf(cc.y, cc.y, csq[i]);
            csq[i] = fmaf(cc.z, cc.z, csq[i]);
            csq[i] = fmaf(cc.w, cc.w, csq[i]);
#pragma unroll
            for (int p = 0; p < 8; p++) {
                float tt = dot[i][p];
                tt = fmaf(cc.x, zz[p].x, tt);
                tt = fmaf(cc.y, zz[p].y, tt);
                tt = fmaf(cc.z, zz[p].z, tt);
                tt = fmaf(cc.w, zz[p].w, tt);
                dot[i][p] = tt;
            }
        }
    }
#pragma unroll
    for (int p = 0; p < 8; p++) {
        float zn = szn[h * 8 + p];
        float bd = 3.4e38f; int bi = 0;
#pragma unroll
        for (int i = 0; i < 2; i++) {
            float dist = zn + csq[i] - 2.f * dot[i][p];
            int idx = half * 256 + q * 64 + lane + i * 32;
            if (dist < bd) { bd = dist; bi = idx; }
        }
#pragma unroll
        for (int off = 16; off > 0; off >>= 1) {
            float od = __shfl_down_sync(0xffffffffu, bd, off);
            int   oi = __shfl_down_sync(0xffffffffu, bi, off);
            if (od < bd || (od == bd && oi < bi)) { bd = od; bi = oi; }
        }
        if (lane == 0) {
            red[((h * 8 + p) * 4 + q) * 2]     = bd;
            red[((h * 8 + p) * 4 + q) * 2 + 1] = __int_as_float(bi);
        }
    }
    __syncthreads();
    if (tid < 16) {
        float bd = 3.4e38f; int bi = 0;
#pragma unroll
        for (int qq = 0; qq < 4; qq++) {
            float od = red[(tid * 4 + qq) * 2];
            int   oi = __float_as_int(red[(tid * 4 + qq) * 2 + 1]);
            if (od < bd || (od == bd && oi < bi)) { bd = od; bi = oi; }
        }
        unsigned long long key = (((unsigned long long)__float_as_uint(bd)) << 32)
                               | (unsigned long long)(unsigned)bi;
        atomicMin(&g_best[pg * 16 + tid], key);
    }
}

// ---------------- decoder 1x1 dproj + relu, ILP-8, 16 positions/block ----------------
__global__ __launch_bounds__(256) void k_dec_r(const float* __restrict__ cb,
                                               const float* __restrict__ dpw,
                                               const float* __restrict__ dpb) {
    __shared__ float sdw[128 * 65];     // weights [c][d]
    __shared__ float scrT[64 * 20];     // codes transposed [d][16 pl], stride 20
    __shared__ float srr[16][128];
    int tid = threadIdx.x;   // 256
    int blk = blockIdx.x;    // 128 blocks x 16 positions
    for (int i = tid; i < 128 * 64; i += 256) {
        int c = i >> 6, d = i & 63;
        sdw[c * 65 + d] = dpw[i];
    }
    for (int i = tid; i < 16 * 64; i += 256) {
        int pl = i >> 6, d = i & 63;
        int p = blk * 16 + pl;
        int idx = (int)(g_best[p] & 0xFFFFFFFFull);
        scrT[d * 20 + pl] = cb[idx * 64 + d];
    }
    __syncthreads();
    int c = tid & 127, grp = tid >> 7;   // grp: pl 0..7 or 8..15
    float bv = dpb[c];
    float acc[8];
#pragma unroll
    for (int l = 0; l < 8; l++) acc[l] = bv;
#pragma unroll 4
    for (int d = 0; d < 64; d++) {
        float wv = sdw[c * 65 + d];
        float4 s0 = *(const float4*)(scrT + d * 20 + grp * 8);
        float4 s1 = *(const float4*)(scrT + d * 20 + grp * 8 + 4);
        acc[0] = fmaf(wv, s0.x, acc[0]);
        acc[1] = fmaf(wv, s0.y, acc[1]);
        acc[2] = fmaf(wv, s0.z, acc[2]);
        acc[3] = fmaf(wv, s0.w, acc[3]);
        acc[4] = fmaf(wv, s1.x, acc[4]);
        acc[5] = fmaf(wv, s1.y, acc[5]);
        acc[6] = fmaf(wv, s1.z, acc[6]);
        acc[7] = fmaf(wv, s1.w, acc[7]);
    }
#pragma unroll
    for (int l = 0; l < 8; l++)
        srr[grp * 8 + l][c] = fmaxf(acc[l], 0.f);
    __syncthreads();
    for (int i = tid; i < 16 * 64; i += 256) {
        int pl = i >> 6, pr = i & 63;
        float x0 = srr[pl][2 * pr], x1 = srr[pl][2 * pr + 1];
        uint32_t hi, lo;
        split_pair(x0, x1, hi, lo);
        int b8 = pr >> 3, ii = pr & 7;
        int pos = b8 * 8 + ((ii < 4) ? 2 * ii : 2 * ii - 7);
        int p = blk * 16 + pl;
        g_rh[p * 64 + pos] = hi;
        g_rl[p * 64 + pos] = lo;
    }
}

// ---------------- q = r @ wt1 per tap, tensor fp16x2 (double-buffered, 3-pass) ----------------
#define QM_SMEM_MAIN (2 * C2_BUFB)
__device__ __forceinline__ void qm_load_stage(uint32_t smb, int buf, int s,
                                              int gt, int t, int tid) {
    uint32_t bb = smb + buf * C2_BUFB;
#pragma unroll
    for (int j = 0; j < 4; j++) {
        int c = j * 256 + tid;
        int m = c >> 3, q = c & 7;
        int kind = q >> 2, u = q & 3;
        const uint32_t* gbase = kind ? g_rl : g_rh;
        cp16(bb + m * 144 + kind * 64 + u * 16,
             gbase + (gt * 128 + m) * 64 + s * 16 + u * 4, 16u);
    }
#pragma unroll
    for (int j = 0; j < 4; j++) {
        int c = j * 256 + tid;
        cp16(bb + C2_AT + c * 16, g_wt1B + (t * 4 + s) * 4096 + c * 4, 16u);
    }
    CP_COMMIT;
}

__global__ __launch_bounds__(256, 2) void k_qm() {
    extern __shared__ char sm[];
    uint32_t smb = smem_u32(sm);
    int tid = threadIdx.x;
    int warp = tid >> 5, lane = tid & 31;
    int wm = warp >> 1, wn = warp & 1;
    int lg = lane >> 2, lt = lane & 3;
    int gt = blockIdx.x, t = blockIdx.y;

    float acc[2][8][4];
#pragma unroll
    for (int mi = 0; mi < 2; mi++)
#pragma unroll
        for (int ni = 0; ni < 8; ni++)
#pragma unroll
            for (int r = 0; r < 4; r++) acc[mi][ni][r] = 0.f;

    qm_load_stage(smb, 0, 0, gt, t, tid);
    for (int s = 0; s < 4; s++) {
        int buf = s & 1;
        if (s + 1 < 4) qm_load_stage(smb, buf ^ 1, s + 1, gt, t, tid);
        if (s + 1 < 4) { CP_WAIT(1); } else { CP_WAIT(0); }
        __syncthreads();
        const uint32_t* As = (const uint32_t*)(sm + buf * C2_BUFB);
        const uint32_t* Bs = (const uint32_t*)(sm + buf * C2_BUFB + C2_AT);
#pragma unroll
        for (int kc = 0; kc < 2; kc++) {
            uint32_t ahi[2][4], alo[2][4];
#pragma unroll
            for (int mi = 0; mi < 2; mi++) {
                int r = wm * 32 + mi * 16 + lg;
                uint2 h0 = *(const uint2*)(As + r * 36 + kc * 8 + 2 * lt);
                uint2 h1 = *(const uint2*)(As + (r + 8) * 36 + kc * 8 + 2 * lt);
                uint2 l0 = *(const uint2*)(As + r * 36 + 16 + kc * 8 + 2 * lt);
                uint2 l1 = *(const uint2*)(As + (r + 8) * 36 + 16 + kc * 8 + 2 * lt);
                ahi[mi][0] = h0.x; ahi[mi][1] = h1.x; ahi[mi][2] = h0.y; ahi[mi][3] = h1.y;
                alo[mi][0] = l0.x; alo[mi][1] = l1.x; alo[mi][2] = l0.y; alo[mi][3] = l1.y;
            }
            uint32_t bh[8][2], bl[8][2];
#pragma unroll
            for (int ni = 0; ni < 8; ni++) {
                uint4 bv = *(const uint4*)(Bs + (((wn * 2 + kc) * 8 + ni) * 32 + lane) * 4);
                bh[ni][0] = bv.x; bh[ni][1] = bv.y;
                bl[ni][0] = bv.z; bl[ni][1] = bv.w;
            }
#pragma unroll
            for (int ni = 0; ni < 8; ni++)
#pragma unroll
                for (int mi = 0; mi < 2; mi++)
                    mma16816(acc[mi][ni], ahi[mi], bh[ni]);
#pragma unroll
            for (int ni = 0; ni < 8; ni++)
#pragma unroll
                for (int mi = 0; mi < 2; mi++)
                    mma16816(acc[mi][ni], alo[mi], bh[ni]);
#pragma unroll
            for (int ni = 0; ni < 8; ni++)
#pragma unroll
                for (int mi = 0; mi < 2; mi++)
                    mma16816(acc[mi][ni], ahi[mi], bl[ni]);
        }
        __syncthreads();
    }
    float* eb = (float*)sm;
#pragma unroll
    for (int mi = 0; mi < 2; mi++)
#pragma unroll
        for (int ni = 0; ni < 8; ni++) {
            int m = wm * 32 + mi * 16 + lg;
            int oc = wn * 64 + ni * 8 + 2 * lt;
            eb[m * 132 + oc]           = acc[mi][ni][0];
            eb[m * 132 + oc + 1]       = acc[mi][ni][1];
            eb[(m + 8) * 132 + oc]     = acc[mi][ni][2];
            eb[(m + 8) * 132 + oc + 1] = acc[mi][ni][3];
        }
    __syncthreads();
    for (int i = tid; i < 4096; i += 256) {
        int m = i >> 5, o4 = i & 31;
        float4 v;
        v.x = eb[m * 132 + o4 * 4];
        v.y = eb[m * 132 + o4 * 4 + 1];
        v.z = eb[m * 132 + o4 * 4 + 2];
        v.w = eb[m * 132 + o4 * 4 + 3];
        *(float4*)(g_q + (t * 2048 + gt * 128 + m) * 128 + o4 * 4) = v;
    }
}

// ---------------- per-block pixel types + FUSED x_hat scatter + idx/loss tail ----------------
// grid: [0,2048) xblk blocks; [2048,2064) idx tail (128 thr each); 2064 loss block.
__global__ void k_xblk(const float* __restrict__ b1d, const float* __restrict__ dw2,
                       const float* __restrict__ db2, float* __restrict__ dout, int wout) {
    if (blockIdx.x >= 2048) {
        if (!wout) return;
        int tid = threadIdx.x;
        if (blockIdx.x < 2064) {
            int fid = (blockIdx.x - 2048) * 128 + tid;
            dout[OFF_IDX + fid] = (float)(unsigned)(g_best[fid] & 0xFFFFFFFFull);
        } else {
            __shared__ float sred[128];
            float s = 0.f;
#pragma unroll
            for (int k = 0; k < 16; k++) {
                int p = k * 128 + tid;
                s += __uint_as_float((unsigned)(g_best[p] >> 32));
            }
            sred[tid] = s;
            __syncthreads();
            for (int off = 64; off > 0; off >>= 1) {
                if (tid < off) sred[tid] += sred[tid + off];
                __syncthreads();
            }
            if (tid == 0) dout[OFF_LOSS] = 1.25f * sred[0] * (1.0f / 131072.0f);
        }
        return;
    }
    __shared__ float sz[9 * 132];
    __shared__ float sxo[27];
    __shared__ float sw2[3 * 128];
    int g = blockIdx.x;
    int n = g >> 6, bi = (g >> 3) & 7, bj = g & 7;
    int o = threadIdx.x;
    for (int i = o; i < 384; i += 128) sw2[i] = dw2[i];
    float bo = b1d[o];
    float s[3][3];
#pragma unroll
    for (int ti = 0; ti < 3; ti++)
#pragma unroll
        for (int tj = 0; tj < 3; tj++) s[ti][tj] = bo;
    const int OFF[3][2]  = {{-1, 0}, {0, 0}, {1, 0}};
    const int MSK[3][2]  = {{1, 6}, {7, 0}, {4, 3}};
#pragma unroll
    for (int di = 0; di < 3; di++)
#pragma unroll
        for (int dj = 0; dj < 3; dj++) {
            const float* qb = g_q + ((di * 3 + dj) * 2048 + n * 64) * 128 + o;
#pragma unroll
            for (int a = 0; a < 2; a++) {
                int tim = MSK[di][a];
                if (tim == 0) continue;
                int roff = OFF[di][a];
                int bi2 = bi + roff;
#pragma unroll
                for (int bb = 0; bb < 2; bb++) {
                    int tjm = MSK[dj][bb];
                    if (tjm == 0) continue;
                    int coff = OFF[dj][bb];
                    int bj2 = bj + coff;
                    float v = 0.f;
                    if (bi2 >= 0 && bi2 < 8 && bj2 >= 0 && bj2 < 8)
                        v = qb[(bi2 * 8 + bj2) * 128];
#pragma unroll
                    for (int ti = 0; ti < 3; ti++)
                        if ((tim >> ti) & 1)
#pragma unroll
                            for (int tj = 0; tj < 3; tj++)
                                if ((tjm >> tj) & 1) s[ti][tj] += v;
                }
            }
        }
#pragma unroll
    for (int ti = 0; ti < 3; ti++)
#pragma unroll
        for (int tj = 0; tj < 3; tj++)
            sz[(ti * 3 + tj) * 132 + o] = fmaxf(s[ti][tj], 0.f);
    __syncthreads();
    if (o < 27) {
        int ty = o / 3, co = o % 3;
        float acc = db2[co];
#pragma unroll 4
        for (int c = 0; c < 128; c++)
            acc = fmaf(sw2[co * 128 + c], sz[ty * 132 + c], acc);
        sxo[ty * 3 + co] = acc;
    }
    __syncthreads();
    float* xb = dout + ((size_t)n * 3) * 16384 + (bi * 16) * 128 + bj * 16;
    for (int e = o; e < 768; e += 128) {
        int j = e & 15, i2 = (e >> 4) & 15, c = e >> 8;
        int ti = (i2 == 0) ? 0 : ((i2 == 15) ? 2 : 1);
        int tj = (j == 0) ? 0 : ((j == 15) ? 2 : 1);
        xb[(c * 128 + i2) * 128 + j] = sxo[(ti * 3 + tj) * 3 + c];
    }
}

// ---------------- launcher ----------------
extern "C" void kernel_launch(void* const* d_in, const int* in_sizes, int n_in,
                              void* d_out, int out_size) {
    const float* x   = (const float*)d_in[0];
    const float* w1  = (const float*)d_in[1];
    const float* b1  = (const float*)d_in[2];
    const float* w2  = (const float*)d_in[3];
    const float* b2  = (const float*)d_in[4];
    const float* pw  = (const float*)d_in[5];
    const float* pb  = (const float*)d_in[6];
    const float* cb  = (const float*)d_in[7];
    const float* dpw = (const float*)d_in[8];
    const float* dpb = (const float*)d_in[9];
    const float* w1d = (const float*)d_in[10];
    const float* b1d = (const float*)d_in[11];
    const float* dw2 = (const float*)d_in[12];
    const float* db2 = (const float*)d_in[13];
    float* out = (float*)d_out;

    cudaFuncSetAttribute(k_conv2m, cudaFuncAttributeMaxDynamicSharedMemorySize, C2_SMEM);
    cudaFuncSetAttribute(k_qm, cudaFuncAttributeMaxDynamicSharedMemorySize, QM_SMEM_MAIN);
    cudaFuncSetAttribute(k_vq, cudaFuncAttributeMaxDynamicSharedMemorySize, VQ_SMEMF * 4);

    int wout = (out_size >= OUT_FULL) ? 1 : 0;

    k_conv1p<<<1088, 256>>>(x, w1, b1, w2, w1d);            // 1 (conv1 + prep + init)
    k_conv2m<<<256, 256, C2_SMEM>>>(b2, pw, pb, out, wout); // 2
    k_vq<<<256, 256, VQ_SMEMF * 4>>>(cb);                   // 3
    k_dec_r<<<128, 256>>>(cb, dpw, dpb);                    // 4  <- profiled
    k_qm<<<dim3(16, 9), 256, QM_SMEM_MAIN>>>();             // 5
    k_xblk<<<2065, 128>>>(b1d, dw2, db2, out, wout);        // 6
}